// round 4
// baseline (speedup 1.0000x reference)
#include <cuda_runtime.h>
#include <cstdint>

// ---------------------------------------------------------------------------
// BiLSTM: B=128, S=1024, D=128, H=256.
// concat[b,k] = x[k,t,b] (k<128)  |  h[b,k-128]  (source transpose quirk, B==D)
//
// 16 clusters x 8 CTAs, 1 CTA/SM, 229 KB smem (W slice 128x384 resident).
// NEW (R3): 512 threads/CTA, K-split GEMM — group 0 handles k<192, group 1
// k>=192; partials combined in zbuf. Doubles warps/SMSP (2->4) to hide the
// LDS->FFMA2 latency that capped issue at 31%.
// ---------------------------------------------------------------------------

namespace {
constexpr int Bsz = 128, Ssz = 1024, Dsz = 128, Hsz = 256, Ksz = 384;
constexpr int NB  = 16;    // batches per cluster
constexpr int CL  = 8;     // CTAs per cluster
constexpr int RWS = 128;   // gate rows per CTA (4 gates x 32 hidden)
constexpr int JSL = 32;    // hidden units per CTA
constexpr int KH  = Ksz / 2;  // 192 k per thread-group

constexpr int W_ELE = Ksz * RWS;   // 49152 floats (192 KB)
constexpr int C_ELE = Ksz * NB;    // 6144  floats (24 KB)
constexpr int Z_ELE = RWS * NB;    // 2048  floats (8 KB)
constexpr int SMEM_BYTES = (W_ELE + C_ELE + Z_ELE) * 4;  // 229376 B

constexpr long long OUT_MAIN = (long long)Bsz * Ssz * 2 * Hsz;
constexpr long long OUT_FULL = OUT_MAIN + 4LL * Bsz * Hsz;
}

__device__ __forceinline__ uint32_t smem_u32(const void* p) {
    uint32_t a;
    asm("{ .reg .u64 t; cvta.to.shared.u64 t, %1; cvt.u32.u64 %0, t; }"
        : "=r"(a) : "l"(p));
    return a;
}

__device__ __forceinline__ float sigm(float v)  { return 1.0f / (1.0f + __expf(-v)); }
__device__ __forceinline__ float tanhf_(float v){ return 1.0f - 2.0f / (__expf(2.0f * v) + 1.0f); }

#define CLUSTER_SYNC() do {                                            \
    asm volatile("barrier.cluster.arrive.aligned;" ::: "memory");      \
    asm volatile("barrier.cluster.wait.aligned;"   ::: "memory");      \
} while (0)

__global__ void __launch_bounds__(512, 1) __cluster_dims__(CL, 1, 1)
bilstm_kernel(const float* __restrict__ x,
              const float* __restrict__ Wf, const float* __restrict__ bf,
              const float* __restrict__ Wb, const float* __restrict__ bb,
              float* __restrict__ out, int write_states)
{
    extern __shared__ float sm[];
    float* Wsm  = sm;              // [k][128]
    float* cbuf = sm + W_ELE;      // [k][16]
    float* zbuf = cbuf + C_ELE;    // [row][16]

    const int tid   = threadIdx.x;
    const int grp   = tid >> 8;             // 0: k<192, 1: k>=192
    const int ltid  = tid & 255;
    const int rank  = blockIdx.x & 7;
    const int cid   = blockIdx.x >> 3;
    const int dir   = cid >> 3;
    const int bg    = (cid & 7) * NB;

    const float* W    = dir ? Wb : Wf;
    const float* bias = dir ? bb : bf;

    // --- load resident weight slice (once) ---
    for (int i = tid; i < RWS * Ksz; i += 512) {
        int r = i / Ksz, k = i - r * Ksz;
        int g = r >> 5, jl = r & 31;
        Wsm[k * RWS + r] = W[(g * Hsz + rank * JSL + jl) * Ksz + k];
    }
    // h := 0
    for (int i = tid; i < Hsz * NB; i += 512) cbuf[Dsz * NB + i] = 0.f;

    // x slice for step 0: cbuf[k][b] = x[k, tt0, bg+b]; each thread owns 16B
    const int prow = tid >> 2, pq = (tid & 3) * 4;
    {
        int tt0 = dir ? (Ssz - 1) : 0;
        const float4* src = (const float4*)(x + (size_t)prow * Ssz * Dsz
                                              + (size_t)tt0 * Dsz + bg + pq);
        *(float4*)(cbuf + prow * NB + pq) = src[0];
    }

    // GEMM thread tiling within the 256-thread logical grid:
    // rows 4*rg..4*rg+3  x  cols 2*cg..2*cg+1, k range selected by grp
    const int rg = ltid >> 3;           // 0..31 (epilogue hidden idx j)
    const int cg = ltid & 7;            // 0..7
    const int hg = rank * JSL + rg;
    const float bsf = bias[0 * Hsz + hg], bsi = bias[1 * Hsz + hg],
                bsc = bias[2 * Hsz + hg], bso = bias[3 * Hsz + hg];

    const uint32_t smb   = smem_u32(sm);
    const uint32_t wA    = smb + rg * 16 + (uint32_t)(grp * KH * RWS) * 4;
    const uint32_t cA    = smb + (uint32_t)W_ELE * 4 + cg * 8
                         + (uint32_t)(grp * KH * NB) * 4;
    const uint32_t zA    = smb + (uint32_t)(W_ELE + C_ELE) * 4;
    const uint32_t haddr = smb + (uint32_t)(W_ELE + (Dsz + hg) * NB) * 4 + cg * 8;

    float c0s = 0.f, c1s = 0.f;

    __syncthreads();

    for (int step = 0; step < Ssz; ++step) {
        const int  tt = dir ? (Ssz - 1 - step) : step;
        const bool pf = (step + 1 < Ssz);

        // prefetch next timestep x slice into registers
        float4 p0;
        if (pf) {
            const int ttn = dir ? (tt - 1) : (tt + 1);
            const float4* src = (const float4*)(x + (size_t)prow * Ssz * Dsz
                                                  + (size_t)ttn * Dsz + bg + pq);
            p0 = src[0];
        }

        // ---- GEMM over this group's half of K ----
        unsigned long long a0 = 0ull, a1 = 0ull, a2 = 0ull, a3 = 0ull;
        uint32_t wa = wA, ca = cA;
        #pragma unroll 8
        for (int k = 0; k < KH; ++k) {
            unsigned long long w01, w23;
            float cv0, cv1;
            asm volatile("ld.shared.v2.u64 {%0,%1},[%2];"
                         : "=l"(w01), "=l"(w23) : "r"(wa));
            asm volatile("ld.shared.v2.f32 {%0,%1},[%2];"
                         : "=f"(cv0), "=f"(cv1) : "r"(ca));
            unsigned long long cc0, cc1;
            uint32_t u0 = __float_as_uint(cv0), u1 = __float_as_uint(cv1);
            asm("mov.b64 %0,{%1,%1};" : "=l"(cc0) : "r"(u0));
            asm("mov.b64 %0,{%1,%1};" : "=l"(cc1) : "r"(u1));
            asm("fma.rn.f32x2 %0,%1,%2,%0;" : "+l"(a0) : "l"(w01), "l"(cc0));
            asm("fma.rn.f32x2 %0,%1,%2,%0;" : "+l"(a1) : "l"(w23), "l"(cc0));
            asm("fma.rn.f32x2 %0,%1,%2,%0;" : "+l"(a2) : "l"(w01), "l"(cc1));
            asm("fma.rn.f32x2 %0,%1,%2,%0;" : "+l"(a3) : "l"(w23), "l"(cc1));
            wa += RWS * 4; ca += NB * 4;
        }

        // unpack accumulators
        float a0l, a0h, a1l, a1h, a2l, a2h, a3l, a3h;
        {
            uint32_t lo, hi;
            asm("mov.b64 {%0,%1},%2;" : "=r"(lo), "=r"(hi) : "l"(a0));
            a0l = __uint_as_float(lo); a0h = __uint_as_float(hi);
            asm("mov.b64 {%0,%1},%2;" : "=r"(lo), "=r"(hi) : "l"(a1));
            a1l = __uint_as_float(lo); a1h = __uint_as_float(hi);
            asm("mov.b64 {%0,%1},%2;" : "=r"(lo), "=r"(hi) : "l"(a2));
            a2l = __uint_as_float(lo); a2h = __uint_as_float(hi);
            asm("mov.b64 {%0,%1},%2;" : "=r"(lo), "=r"(hi) : "l"(a3));
            a3l = __uint_as_float(lo); a3h = __uint_as_float(hi);
        }

        const int r0 = rg * 4, b0 = cg * 2;
        float* zp = (float*)(size_t)0;  // silence unused warning path
        (void)zp;

        if (grp == 0) {
            // group 0 initializes zbuf with its partials
            *(float2*)(zbuf + (r0 + 0) * NB + b0) = make_float2(a0l, a2l);
            *(float2*)(zbuf + (r0 + 1) * NB + b0) = make_float2(a0h, a2h);
            *(float2*)(zbuf + (r0 + 2) * NB + b0) = make_float2(a1l, a3l);
            *(float2*)(zbuf + (r0 + 3) * NB + b0) = make_float2(a1h, a3h);
        }
        __syncthreads();
        if (grp == 1) {
            // group 1 accumulates its partials on top
            float2* z0 = (float2*)(zbuf + (r0 + 0) * NB + b0);
            float2* z1 = (float2*)(zbuf + (r0 + 1) * NB + b0);
            float2* z2 = (float2*)(zbuf + (r0 + 2) * NB + b0);
            float2* z3 = (float2*)(zbuf + (r0 + 3) * NB + b0);
            float2 v0 = *z0, v1 = *z1, v2 = *z2, v3 = *z3;
            v0.x += a0l; v0.y += a2l;  *z0 = v0;
            v1.x += a0h; v1.y += a2h;  *z1 = v1;
            v2.x += a1l; v2.y += a3l;  *z2 = v2;
            v3.x += a1h; v3.y += a3h;  *z3 = v3;
        }

        // barrier #1: z complete per-CTA; cluster-wide all GEMM reads done
        CLUSTER_SYNC();

        // safe to overwrite our x rows with the next timestep
        if (pf) *(float4*)(cbuf + prow * NB + pq) = p0;

        // ---- epilogue: logical 256-thread grid (grp 0 threads) ----
        if (tid < 256) {
            const int j = rg;
            float2 zF = *(float2*)(zbuf + (      j) * NB + b0);
            float2 zI = *(float2*)(zbuf + ( 32 + j) * NB + b0);
            float2 zC = *(float2*)(zbuf + ( 64 + j) * NB + b0);
            float2 zO = *(float2*)(zbuf + ( 96 + j) * NB + b0);

            float f0 = sigm(zF.x + bsf),  f1 = sigm(zF.y + bsf);
            float i0 = sigm(zI.x + bsi),  i1 = sigm(zI.y + bsi);
            float g0 = tanhf_(zC.x + bsc), g1 = tanhf_(zC.y + bsc);
            float o0 = sigm(zO.x + bso),  o1 = sigm(zO.y + bso);

            c0s = f0 * c0s + i0 * g0;
            c1s = f1 * c1s + i1 * g1;
            float h0 = o0 * tanhf_(c0s);
            float h1 = o1 * tanhf_(c1s);

            // broadcast h slice to every CTA's concat buffer (DSMEM push)
            if (pf) {
                unsigned long long hp;
                uint32_t hu0 = __float_as_uint(h0), hu1 = __float_as_uint(h1);
                asm("mov.b64 %0,{%1,%2};" : "=l"(hp) : "r"(hu0), "r"(hu1));
                #pragma unroll
                for (int p = 0; p < CL; ++p) {
                    uint32_t ra;
                    asm("mapa.shared::cluster.u32 %0,%1,%2;"
                        : "=r"(ra) : "r"(haddr), "r"(p));
                    asm volatile("st.shared::cluster.b64 [%0],%1;"
                                 :: "r"(ra), "l"(hp) : "memory");
                }
            }

            // output[b, tt, dir*H + hg]
            size_t obase = ((size_t)(bg + b0) * Ssz + (size_t)tt) * (2 * Hsz)
                           + (size_t)dir * Hsz + hg;
            out[obase]                         = h0;
            out[obase + (size_t)Ssz * 2 * Hsz] = h1;

            if (step == Ssz - 1 && write_states) {
                size_t hb = (size_t)OUT_MAIN
                          + ((size_t)dir * Bsz + bg + b0) * Hsz + hg;
                out[hb]       = h0;
                out[hb + Hsz] = h1;
                size_t cb = hb + 2 * (size_t)Bsz * Hsz;
                out[cb]       = c0s;
                out[cb + Hsz] = c1s;
            }
        }

        // barrier #2: all h_next writes visible cluster-wide before next GEMM
        CLUSTER_SYNC();
    }
    (void)zA;
}

extern "C" void kernel_launch(void* const* d_in, const int* in_sizes, int n_in,
                              void* d_out, int out_size)
{
    const float* x  = (const float*)d_in[0];
    const float* Wf = (const float*)d_in[1];
    const float* bf = (const float*)d_in[2];
    const float* Wb = (const float*)d_in[3];
    const float* bb = (const float*)d_in[4];

    cudaFuncSetAttribute(bilstm_kernel,
                         cudaFuncAttributeMaxDynamicSharedMemorySize, SMEM_BYTES);

    int ws = ((long long)out_size >= OUT_FULL) ? 1 : 0;
    bilstm_kernel<<<128, 512, SMEM_BYTES>>>(x, Wf, bf, Wb, bb, (float*)d_out, ws);
}

// round 9
// speedup vs baseline: 1.1076x; 1.1076x over previous
#include <cuda_runtime.h>
#include <cuda_bf16.h>
#include <cstdint>

// ---------------------------------------------------------------------------
// BiLSTM B=128,S=1024,D=128,H=256 — R7: warp-level mma.sync bf16 3-term split.
// The harness compiles PTX for target sm_103 (NO 'a' suffix) -> all tcgen05 /
// .cta_group features are unavailable (R7 ptxas errors). Fallback tensor path:
// mma.sync.aligned.m16n8k16 bf16 (sm_80+ PTX), which still beats the FFMA2
// ceiling by ~8x. Cluster skeleton identical to the PASSING R3 kernel (plain
// sm_90 features only: mapa / st.shared::cluster / barrier.cluster).
//
// concat[b,k] = x[k,t,b] (k<128) | h[b,k-128]   (source transpose quirk)
//
// 16 clusters x 8 CTAs (1 CTA/SM, 230400 B smem). CTA owns 128 gate-rows
// (4 gates x 32 hidden) of W, resident as bf16 hi+lo in packed 16x16
// ldmatrix tiles (conflict-free LDSM, zero padding). Per step, warp w:
//   D[16x16] += Whi@Chi + Whi@Clo + Wlo@Chi  over K=384 (24 k-tiles,
//   6 HMMA + 4 LDSM per k-tile). D staged to zbuf, fp32 epilogue, h pushed
//   cluster-wide via st.shared::cluster. Two cluster barriers per step.
// ---------------------------------------------------------------------------

namespace {
constexpr int Bsz = 128, Ssz = 1024, Dsz = 128, Hsz = 256, Ksz = 384;
constexpr int NB = 16, CL = 8;

constexpr uint32_t ATILE = 128 * 384 * 2;          // 98304 per split
constexpr uint32_t ATHI  = 0;
constexpr uint32_t ATLO  = ATILE;
constexpr uint32_t CSZ   = 384 * 16 * 2;           // 12288 per split
constexpr uint32_t CHI   = 2 * ATILE;              // 196608
constexpr uint32_t CLO   = CHI + CSZ;              // 208896
constexpr uint32_t ZBo   = CLO + CSZ;              // 221184
constexpr int ZSTR = 18;                           // zbuf row stride (floats)
constexpr int SMEM_DYN = (int)ZBo + 128 * ZSTR * 4;  // 230400

constexpr long long OUT_MAIN = (long long)Bsz * Ssz * 2 * Hsz;
constexpr long long OUT_FULL = OUT_MAIN + 4LL * Bsz * Hsz;
}

__device__ __forceinline__ uint32_t smem_u32(const void* p) {
    uint32_t a;
    asm("{ .reg .u64 t; cvta.to.shared.u64 t, %1; cvt.u32.u64 %0, t; }"
        : "=r"(a) : "l"(p));
    return a;
}

// A (W) packed-tile offset: row r in [0,128), col k in [0,384).
// tile(w=r>>4, kt=k>>4) is 512 B; inside: four 8x8 b16 matrices in
// a0,a1,a2,a3 order: m = (kk>>3)*2 + (rr>>3); then row-major 8x16B.
__device__ __forceinline__ uint32_t aoff(int r, int k) {
    uint32_t w = (uint32_t)(r >> 4), rr = (uint32_t)(r & 15);
    uint32_t kt = (uint32_t)(k >> 4), kk = (uint32_t)(k & 15);
    uint32_t m = ((kk >> 3) << 1) + (rr >> 3);
    return (w * 24u + kt) * 512u + m * 128u + (rr & 7u) * 16u + (kk & 7u) * 2u;
}

__device__ __forceinline__ float sigm(float v)  { return 1.0f / (1.0f + __expf(-v)); }
__device__ __forceinline__ float tanhf_(float v){ return 1.0f - 2.0f / (__expf(2.0f * v) + 1.0f); }

__device__ __forceinline__ void split_bf16(float v, uint16_t& hi, uint16_t& lo) {
    __nv_bfloat16 h = __float2bfloat16(v);
    __nv_bfloat16 l = __float2bfloat16(v - __bfloat162float(h));
    hi = __bfloat16_as_ushort(h);
    lo = __bfloat16_as_ushort(l);
}

#define LDSM4(r0,r1,r2,r3,addr) \
    asm volatile("ldmatrix.sync.aligned.m8n8.x4.shared.b16 {%0,%1,%2,%3},[%4];" \
        : "=r"(r0),"=r"(r1),"=r"(r2),"=r"(r3) : "r"(addr))
#define LDSM4T(r0,r1,r2,r3,addr) \
    asm volatile("ldmatrix.sync.aligned.m8n8.x4.trans.shared.b16 {%0,%1,%2,%3},[%4];" \
        : "=r"(r0),"=r"(r1),"=r"(r2),"=r"(r3) : "r"(addr))
#define MMA16816(d,a,b0,b1) \
    asm volatile("mma.sync.aligned.m16n8k16.row.col.f32.bf16.bf16.f32 " \
        "{%0,%1,%2,%3},{%4,%5,%6,%7},{%8,%9},{%0,%1,%2,%3};" \
        : "+f"((d)[0]),"+f"((d)[1]),"+f"((d)[2]),"+f"((d)[3]) \
        : "r"((a)[0]),"r"((a)[1]),"r"((a)[2]),"r"((a)[3]),"r"(b0),"r"(b1))

__global__ void __launch_bounds__(256, 1) __cluster_dims__(CL, 1, 1)
bilstm_mma(const float* __restrict__ x,
           const float* __restrict__ Wf, const float* __restrict__ bf,
           const float* __restrict__ Wb, const float* __restrict__ bb,
           float* __restrict__ out, int write_states)
{
    extern __shared__ char smc[];
    const uint32_t smb = smem_u32(smc);

    const int tid  = threadIdx.x;
    const int wid  = tid >> 5;
    const int lane = tid & 31;
    uint32_t myrank;
    asm("mov.u32 %0, %%cluster_ctarank;" : "=r"(myrank));
    const int rank = (int)myrank;
    const int cid  = blockIdx.x >> 3;
    const int dir  = cid >> 3;
    const int bg   = (cid & 7) * NB;

    const float* W    = dir ? Wb : Wf;
    const float* bias = dir ? bb : bf;

    // ---- load W slice, bf16 hi/lo split, into packed ldmatrix tiles ----
    for (int idx = tid; idx < 128 * Ksz; idx += 256) {
        int r = idx / Ksz, k = idx - r * Ksz;
        int gr = (r >> 5) * Hsz + rank * 32 + (r & 31);
        float v = W[(size_t)gr * Ksz + k];
        uint16_t hi, lo; split_bf16(v, hi, lo);
        uint32_t o = aoff(r, k);
        *(uint16_t*)(smc + ATHI + o) = hi;
        *(uint16_t*)(smc + ATLO + o) = lo;
    }
    // zero both C splits (h region must start at 0)
    for (int i = tid; i < (int)(2 * CSZ) / 4; i += 256)
        ((uint32_t*)(smc + CHI))[i] = 0;
    __syncthreads();

    // ---- x staging map: thread -> (k = tid>>1, b0 = (tid&1)*8) ----
    const int kx = tid >> 1, bx0 = (tid & 1) * 8;
    {
        int tt0 = dir ? (Ssz - 1) : 0;
        const float4* src = (const float4*)(x + (size_t)kx * Ssz * Dsz
                                              + (size_t)tt0 * Dsz + bg + bx0);
        float4 v0 = src[0], v1 = src[1];
        #pragma unroll
        for (int i = 0; i < 8; ++i) {
            float v = (i < 4) ? ((const float*)&v0)[i] : ((const float*)&v1)[i - 4];
            uint16_t hi, lo; split_bf16(v, hi, lo);
            uint32_t o = (uint32_t)kx * 32u + (uint32_t)(bx0 + i) * 2u;
            *(uint16_t*)(smc + CHI + o) = hi;
            *(uint16_t*)(smc + CLO + o) = lo;
        }
    }

    // ---- epilogue map: thread -> hidden j = lane, batches (2*wid, 2*wid+1) ----
    const int j  = lane;
    const int bp = 2 * wid;
    const int hg = rank * 32 + j;
    const float bF = bias[0 * Hsz + hg], bI = bias[1 * Hsz + hg],
                bC = bias[2 * Hsz + hg], bO = bias[3 * Hsz + hg];

    // DSMEM push addresses: C[k = 128+hg][bp..bp+1] (one b32) in all 8 CTAs
    uint32_t rHi[CL];
    {
        uint32_t loc = smb + CHI + (uint32_t)(Dsz + hg) * 32u + (uint32_t)bp * 2u;
        #pragma unroll
        for (int p = 0; p < CL; ++p) {
            asm("mapa.shared::cluster.u32 %0,%1,%2;"
                : "=r"(rHi[p]) : "r"(loc), "r"(p));
        }
    }

    // GEMM addressing (per warp, per lane)
    const uint32_t aB = smb + (uint32_t)wid * 24u * 512u
                      + (uint32_t)(lane >> 3) * 128u + (uint32_t)(lane & 7) * 16u;
    const uint32_t bB = smb + CHI
                      + ((uint32_t)((lane >> 3) & 1) * 8u + (uint32_t)(lane & 7)) * 32u
                      + (uint32_t)(lane >> 4) * 16u;

    float* zbuf = (float*)(smc + ZBo);
    const int gid = lane >> 2, tig = lane & 3;

    float c0s = 0.f, c1s = 0.f;

    __syncthreads();

    for (int step = 0; step < Ssz; ++step) {
        const int  tt = dir ? (Ssz - 1 - step) : step;
        const bool pf = (step + 1 < Ssz);

        // prefetch next x into registers
        float4 p0, p1;
        if (pf) {
            const int ttn = dir ? (tt - 1) : (tt + 1);
            const float4* src = (const float4*)(x + (size_t)kx * Ssz * Dsz
                                                  + (size_t)ttn * Dsz + bg + bx0);
            p0 = src[0]; p1 = src[1];
        }

        // ---- GEMM: 24 k-tiles, 3-term bf16 split ----
        float d0[4] = {0.f, 0.f, 0.f, 0.f};
        float d1[4] = {0.f, 0.f, 0.f, 0.f};
        #pragma unroll 4
        for (int kt = 0; kt < 24; ++kt) {
            uint32_t aHi[4], aLo[4], bHi[4], bLo[4];
            uint32_t aA = aB + (uint32_t)kt * 512u;
            uint32_t bA = bB + (uint32_t)kt * 512u;
            LDSM4(aHi[0], aHi[1], aHi[2], aHi[3], aA);
            LDSM4(aLo[0], aLo[1], aLo[2], aLo[3], aA + ATILE);
            LDSM4T(bHi[0], bHi[1], bHi[2], bHi[3], bA);
            LDSM4T(bLo[0], bLo[1], bLo[2], bLo[3], bA + CSZ);
            MMA16816(d0, aHi, bHi[0], bHi[1]);
            MMA16816(d1, aHi, bHi[2], bHi[3]);
            MMA16816(d0, aHi, bLo[0], bLo[1]);
            MMA16816(d1, aHi, bLo[2], bLo[3]);
            MMA16816(d0, aLo, bHi[0], bHi[1]);
            MMA16816(d1, aLo, bHi[2], bHi[3]);
        }

        // ---- stage D to zbuf: rows w*16 + {gid, gid+8}, cols 2tig (+8) ----
        {
            float* zr0 = zbuf + (wid * 16 + gid) * ZSTR;
            float* zr1 = zr0 + 8 * ZSTR;
            *(float2*)(zr0 + 2 * tig)     = make_float2(d0[0], d0[1]);
            *(float2*)(zr1 + 2 * tig)     = make_float2(d0[2], d0[3]);
            *(float2*)(zr0 + 8 + 2 * tig) = make_float2(d1[0], d1[1]);
            *(float2*)(zr1 + 8 + 2 * tig) = make_float2(d1[2], d1[3]);
        }
        __syncthreads();

        // cluster barrier #1 (split): our GEMM reads of C are done
        asm volatile("barrier.cluster.arrive.aligned;" ::: "memory");

        // ---- epilogue: hidden j, batches bp, bp+1 ----
        float2 zF = *(float2*)(zbuf + (0 * 32 + j) * ZSTR + bp);
        float2 zI = *(float2*)(zbuf + (1 * 32 + j) * ZSTR + bp);
        float2 zC = *(float2*)(zbuf + (2 * 32 + j) * ZSTR + bp);
        float2 zO = *(float2*)(zbuf + (3 * 32 + j) * ZSTR + bp);

        float f0 = sigm(zF.x + bF),   f1 = sigm(zF.y + bF);
        float i0 = sigm(zI.x + bI),   i1 = sigm(zI.y + bI);
        float g0 = tanhf_(zC.x + bC), g1 = tanhf_(zC.y + bC);
        float o0 = sigm(zO.x + bO),   o1 = sigm(zO.y + bO);

        c0s = f0 * c0s + i0 * g0;
        c1s = f1 * c1s + i1 * g1;
        float h0 = o0 * tanhf_(c0s);
        float h1 = o1 * tanhf_(c1s);

        // fp32 output: out[bg+bp(+1), tt, dir*H + hg]
        {
            size_t ob = ((size_t)(bg + bp) * Ssz + (size_t)tt) * (2 * Hsz)
                      + (size_t)dir * Hsz + hg;
            out[ob]                         = h0;
            out[ob + (size_t)Ssz * 2 * Hsz] = h1;
        }
        if (!pf && write_states) {
            size_t hb = (size_t)OUT_MAIN
                      + ((size_t)dir * Bsz + bg + bp) * Hsz + hg;
            out[hb]       = h0;
            out[hb + Hsz] = h1;
            size_t cb = hb + 2 * (size_t)Bsz * Hsz;
            out[cb]       = c0s;
            out[cb + Hsz] = c1s;
        }

        // wait: every CTA finished its GEMM -> safe to overwrite C anywhere
        asm volatile("barrier.cluster.wait.aligned;" ::: "memory");

        if (pf) {
            // stage x(t+1) locally
            #pragma unroll
            for (int i = 0; i < 8; ++i) {
                float v = (i < 4) ? ((const float*)&p0)[i]
                                  : ((const float*)&p1)[i - 4];
                uint16_t hi, lo; split_bf16(v, hi, lo);
                uint32_t o = (uint32_t)kx * 32u + (uint32_t)(bx0 + i) * 2u;
                *(uint16_t*)(smc + CHI + o) = hi;
                *(uint16_t*)(smc + CLO + o) = lo;
            }
            // push h pair (bp, bp+1) to all CTAs' C hi/lo
            uint16_t h0h, h0l, h1h, h1l;
            split_bf16(h0, h0h, h0l);
            split_bf16(h1, h1h, h1l);
            uint32_t phi = ((uint32_t)h1h << 16) | h0h;
            uint32_t plo = ((uint32_t)h1l << 16) | h0l;
            #pragma unroll
            for (int p = 0; p < CL; ++p) {
                asm volatile("st.shared::cluster.b32 [%0],%1;"
                             :: "r"(rHi[p]), "r"(phi) : "memory");
                asm volatile("st.shared::cluster.b32 [%0],%1;"
                             :: "r"(rHi[p] + CSZ), "r"(plo) : "memory");
            }
        }

        // cluster barrier #2: all C writes visible before next GEMM
        asm volatile("barrier.cluster.arrive.aligned;" ::: "memory");
        asm volatile("barrier.cluster.wait.aligned;"   ::: "memory");
    }
}

extern "C" void kernel_launch(void* const* d_in, const int* in_sizes, int n_in,
                              void* d_out, int out_size)
{
    const float* x  = (const float*)d_in[0];
    const float* Wf = (const float*)d_in[1];
    const float* bf = (const float*)d_in[2];
    const float* Wb = (const float*)d_in[3];
    const float* bb = (const float*)d_in[4];

    cudaFuncSetAttribute(bilstm_mma,
                         cudaFuncAttributeMaxDynamicSharedMemorySize, SMEM_DYN);

    int ws = ((long long)out_size >= OUT_FULL) ? 1 : 0;
    bilstm_mma<<<128, 256, SMEM_DYN>>>(x, Wf, bf, Wb, bb, (float*)d_out, ws);
}

// round 11
// speedup vs baseline: 1.2263x; 1.1071x over previous
#include <cuda_runtime.h>
#include <cuda_bf16.h>
#include <cstdint>

// ---------------------------------------------------------------------------
// BiLSTM B=128,S=1024,D=128,H=256 — R10: dual-group software pipeline.
// mma.sync m16n8k16 bf16 3-term split (Whi@Chi + Whi@Clo + Wlo@Chi).
// 16 clusters x 8 CTAs (1 CTA/SM). Each cluster's 16 batches split into two
// groups (n=8 each) pipelined so cluster-barrier waits hide behind the other
// group's GEMM/epilogue. One barrier generation per chain-step (was two),
// all waits overlapped.
//   gen alpha: all C0 reads done (+ h1(t-1) pushes posted before it)
//   gen beta : all C1 reads done (+ h0(t)  pushes posted before it)
// ---------------------------------------------------------------------------

namespace {
constexpr int Bsz = 128, Ssz = 1024, Dsz = 128, Hsz = 256, Ksz = 384;
constexpr int CL = 8;

constexpr uint32_t ATILE = 128 * 384 * 2;     // 98304 per W split
constexpr uint32_t CBASE = 2 * ATILE;         // 196608
constexpr uint32_t CS    = 6144;              // one group-split (384k x 8b bf16)
constexpr uint32_t CGRP  = 2 * CS;            // 12288 (hi+lo)
constexpr uint32_t ZB0   = CBASE + 2 * CGRP;  // 221184
constexpr int ZSTRf  = 10;                    // zbuf row stride (floats)
constexpr uint32_t ZGRPB = 128 * ZSTRf * 4;   // 5120 B per group
constexpr int SMEM_DYN = (int)(ZB0 + 2 * ZGRPB);  // 231424

constexpr long long OUT_MAIN = (long long)Bsz * Ssz * 2 * Hsz;
constexpr long long OUT_FULL = OUT_MAIN + 4LL * Bsz * Hsz;
}

__device__ __forceinline__ uint32_t smem_u32(const void* p) {
    uint32_t a;
    asm("{ .reg .u64 t; cvta.to.shared.u64 t, %1; cvt.u32.u64 %0, t; }"
        : "=r"(a) : "l"(p));
    return a;
}

// A (W) packed-tile offset (16x16 tiles of four 8x8 b16 matrices) — as R9.
__device__ __forceinline__ uint32_t aoff(int r, int k) {
    uint32_t w = (uint32_t)(r >> 4), rr = (uint32_t)(r & 15);
    uint32_t kt = (uint32_t)(k >> 4), kk = (uint32_t)(k & 15);
    uint32_t m = ((kk >> 3) << 1) + (rr >> 3);
    return (w * 24u + kt) * 512u + m * 128u + (rr & 7u) * 16u + (kk & 7u) * 2u;
}
// C group tile offset: 24 k-tiles x 256 B; per kt two 8x8 matrices (k-halves),
// each 128 B contiguous -> conflict-free LDSM.x2.trans. b in [0,8).
__device__ __forceinline__ uint32_t coff(int k, int b) {
    uint32_t kt = (uint32_t)(k >> 4), kk = (uint32_t)(k & 15);
    return kt * 256u + (kk >> 3) * 128u + (kk & 7u) * 16u + (uint32_t)b * 2u;
}

__device__ __forceinline__ float sigm(float v)  { return 1.0f / (1.0f + __expf(-v)); }
__device__ __forceinline__ float tanhf_(float v){ return 1.0f - 2.0f / (__expf(2.0f * v) + 1.0f); }

__device__ __forceinline__ void split_bf16(float v, uint16_t& hi, uint16_t& lo) {
    __nv_bfloat16 h = __float2bfloat16(v);
    __nv_bfloat16 l = __float2bfloat16(v - __bfloat162float(h));
    hi = __bfloat16_as_ushort(h);
    lo = __bfloat16_as_ushort(l);
}

#define LDSM4(r0,r1,r2,r3,addr) \
    asm volatile("ldmatrix.sync.aligned.m8n8.x4.shared.b16 {%0,%1,%2,%3},[%4];" \
        : "=r"(r0),"=r"(r1),"=r"(r2),"=r"(r3) : "r"(addr))
#define LDSM2T(r0,r1,addr) \
    asm volatile("ldmatrix.sync.aligned.m8n8.x2.trans.shared.b16 {%0,%1},[%2];" \
        : "=r"(r0),"=r"(r1) : "r"(addr))
#define MMA16816(d,a,b0,b1) \
    asm volatile("mma.sync.aligned.m16n8k16.row.col.f32.bf16.bf16.f32 " \
        "{%0,%1,%2,%3},{%4,%5,%6,%7},{%8,%9},{%0,%1,%2,%3};" \
        : "+f"((d)[0]),"+f"((d)[1]),"+f"((d)[2]),"+f"((d)[3]) \
        : "r"((a)[0]),"r"((a)[1]),"r"((a)[2]),"r"((a)[3]),"r"(b0),"r"(b1))
#define CARRIVE() asm volatile("barrier.cluster.arrive.aligned;" ::: "memory")
#define CWAIT()   asm volatile("barrier.cluster.wait.aligned;"   ::: "memory")

// n=8 GEMM over K=384, 3-term bf16 split. aA/bA: per-lane LDSM base addrs.
__device__ __forceinline__ void gemm_n8(uint32_t aA, uint32_t bA, float* d) {
    #pragma unroll 4
    for (int kt = 0; kt < 24; ++kt) {
        uint32_t aHi[4], aLo[4], b0h, b1h, b0l, b1l;
        uint32_t aAd = aA + (uint32_t)kt * 512u;
        uint32_t bAd = bA + (uint32_t)kt * 256u;
        LDSM4(aHi[0], aHi[1], aHi[2], aHi[3], aAd);
        LDSM4(aLo[0], aLo[1], aLo[2], aLo[3], aAd + ATILE);
        LDSM2T(b0h, b1h, bAd);
        LDSM2T(b0l, b1l, bAd + CS);
        MMA16816(d, aHi, b0h, b1h);
        MMA16816(d, aHi, b0l, b1l);
        MMA16816(d, aLo, b0h, b1h);
    }
}

__global__ void __launch_bounds__(256, 1) __cluster_dims__(CL, 1, 1)
bilstm_pipe(const float* __restrict__ x,
            const float* __restrict__ Wf, const float* __restrict__ bf,
            const float* __restrict__ Wb, const float* __restrict__ bb,
            float* __restrict__ out, int write_states)
{
    extern __shared__ char smc[];
    const uint32_t smb = smem_u32(smc);

    const int tid  = threadIdx.x;
    const int wid  = tid >> 5;
    const int lane = tid & 31;
    uint32_t myrank;
    asm("mov.u32 %0, %%cluster_ctarank;" : "=r"(myrank));
    const int rank = (int)myrank;
    const int cid  = blockIdx.x >> 3;
    const int dir  = cid >> 3;
    const int bg   = (cid & 7) * 16;

    const float* W    = dir ? Wb : Wf;
    const float* bias = dir ? bb : bf;

    // ---- W slice -> packed bf16 hi/lo A tiles ----
    for (int idx = tid; idx < 128 * Ksz; idx += 256) {
        int r = idx / Ksz, k = idx - r * Ksz;
        int gr = (r >> 5) * Hsz + rank * 32 + (r & 31);
        float v = W[(size_t)gr * Ksz + k];
        uint16_t hi, lo; split_bf16(v, hi, lo);
        uint32_t o = aoff(r, k);
        *(uint16_t*)(smc + o)         = hi;
        *(uint16_t*)(smc + ATILE + o) = lo;
    }
    // zero all C group tiles
    for (int i = tid; i < (int)(2 * CGRP) / 4; i += 256)
        ((uint32_t*)(smc + CBASE))[i] = 0;
    __syncthreads();

    // ---- x staging map: thread -> (group gx = tid&1, k row kq = tid>>1) ----
    const int gx = tid & 1, kq = tid >> 1;
    const uint32_t xdst = CBASE + (uint32_t)gx * CGRP + coff(kq, 0);
    {
        int tt0 = dir ? (Ssz - 1) : 0;
        const float4* src = (const float4*)(x + (size_t)kq * Ssz * Dsz
                                              + (size_t)tt0 * Dsz + bg + gx * 8);
        float4 v0 = src[0], v1 = src[1];
        uint16_t hi[8], lo[8];
        #pragma unroll
        for (int i = 0; i < 8; ++i) {
            float v = (i < 4) ? ((const float*)&v0)[i] : ((const float*)&v1)[i - 4];
            split_bf16(v, hi[i], lo[i]);
        }
        uint32_t wh[4], wl[4];
        #pragma unroll
        for (int i = 0; i < 4; ++i) {
            wh[i] = (uint32_t)hi[2*i] | ((uint32_t)hi[2*i+1] << 16);
            wl[i] = (uint32_t)lo[2*i] | ((uint32_t)lo[2*i+1] << 16);
        }
        *(uint4*)(smc + xdst)      = make_uint4(wh[0], wh[1], wh[2], wh[3]);
        *(uint4*)(smc + xdst + CS) = make_uint4(wl[0], wl[1], wl[2], wl[3]);
    }

    // ---- epilogue map: thread -> (j = lane, group ge = wid>>2, bp = 2*(wid&3)) ----
    const int j  = lane;
    const int ge = wid >> 2;
    const int bp = 2 * (wid & 3);
    const int hg = rank * 32 + j;
    const float bF = bias[0 * Hsz + hg], bI = bias[1 * Hsz + hg],
                bC = bias[2 * Hsz + hg], bO = bias[3 * Hsz + hg];

    // DSMEM push addresses: C[ge][k=128+hg][bp..bp+1] (b32) in all 8 CTAs
    uint32_t rHi[CL];
    {
        uint32_t loc = smb + CBASE + (uint32_t)ge * CGRP + coff(Dsz + hg, bp);
        #pragma unroll
        for (int p = 0; p < CL; ++p)
            asm("mapa.shared::cluster.u32 %0,%1,%2;" : "=r"(rHi[p]) : "r"(loc), "r"(p));
    }

    // GEMM per-lane LDSM bases
    const uint32_t aA = smb + (uint32_t)wid * 24u * 512u
                      + (uint32_t)(lane >> 3) * 128u + (uint32_t)(lane & 7) * 16u;
    const uint32_t bA0 = smb + CBASE + (uint32_t)(lane & 15) * 16u;
    const uint32_t bA1 = bA0 + CGRP;

    float* zb0 = (float*)(smc + ZB0);
    float* zb1 = (float*)(smc + ZB0 + ZGRPB);
    const int gid = lane >> 2, tig = lane & 3;

    float c0s = 0.f, c1s = 0.f;  // cell states for (hg, group ge, batches bp, bp+1)

    __syncthreads();
    CARRIVE(); CWAIT();          // init visible cluster-wide

    for (int step = 0; step < Ssz; ++step) {
        const int  tt = dir ? (Ssz - 1 - step) : step;
        const bool pf = (step + 1 < Ssz);

        // prefetch next x (this thread's group gx)
        float4 p0, p1;
        if (pf) {
            const int ttn = dir ? (tt - 1) : (tt + 1);
            const float4* src = (const float4*)(x + (size_t)kq * Ssz * Dsz
                                                  + (size_t)ttn * Dsz + bg + gx * 8);
            p0 = src[0]; p1 = src[1];
        }

        float h0 = 0.f, h1 = 0.f;  // this thread's h outputs (group ge)

        #pragma unroll
        for (int ph = 0; ph < 2; ++ph) {
            // ---- GEMM group ph ----
            float d[4] = {0.f, 0.f, 0.f, 0.f};
            gemm_n8(aA, ph ? bA1 : bA0, d);

            // stage z
            {
                float* zg = ph ? zb1 : zb0;
                float* zr0 = zg + (wid * 16 + gid) * ZSTRf;
                *(float2*)(zr0 + 2 * tig)             = make_float2(d[0], d[1]);
                *(float2*)(zr0 + 8 * ZSTRf + 2 * tig) = make_float2(d[2], d[3]);
            }
            __syncthreads();
            CARRIVE();   // gen: "all C[ph] reads done" (+ prior pushes posted)

            // x-stage for this phase's group (private C region, own reads done)
            if (pf && gx == ph) {
                uint16_t hi[8], lo[8];
                #pragma unroll
                for (int i = 0; i < 8; ++i) {
                    float v = (i < 4) ? ((const float*)&p0)[i]
                                      : ((const float*)&p1)[i - 4];
                    split_bf16(v, hi[i], lo[i]);
                }
                uint32_t wh[4], wl[4];
                #pragma unroll
                for (int i = 0; i < 4; ++i) {
                    wh[i] = (uint32_t)hi[2*i] | ((uint32_t)hi[2*i+1] << 16);
                    wl[i] = (uint32_t)lo[2*i] | ((uint32_t)lo[2*i+1] << 16);
                }
                *(uint4*)(smc + xdst)      = make_uint4(wh[0], wh[1], wh[2], wh[3]);
                *(uint4*)(smc + xdst + CS) = make_uint4(wl[0], wl[1], wl[2], wl[3]);
            }

            // epilogue for this phase's group (threads with ge == ph)
            if (ge == ph) {
                float* zg = ph ? zb1 : zb0;
                float2 zF = *(float2*)(zg + (0 * 32 + j) * ZSTRf + bp);
                float2 zI = *(float2*)(zg + (1 * 32 + j) * ZSTRf + bp);
                float2 zC = *(float2*)(zg + (2 * 32 + j) * ZSTRf + bp);
                float2 zO = *(float2*)(zg + (3 * 32 + j) * ZSTRf + bp);

                float f0 = sigm(zF.x + bF),   f1 = sigm(zF.y + bF);
                float i0 = sigm(zI.x + bI),   i1 = sigm(zI.y + bI);
                float g0 = tanhf_(zC.x + bC), g1 = tanhf_(zC.y + bC);
                float o0 = sigm(zO.x + bO),   o1 = sigm(zO.y + bO);

                c0s = f0 * c0s + i0 * g0;
                c1s = f1 * c1s + i1 * g1;
                h0 = o0 * tanhf_(c0s);
                h1 = o1 * tanhf_(c1s);

                // fp32 outputs
                int bb0 = bg + ph * 8 + bp;
                size_t ob = ((size_t)bb0 * Ssz + (size_t)tt) * (2 * Hsz)
                          + (size_t)dir * Hsz + hg;
                out[ob]                         = h0;
                out[ob + (size_t)Ssz * 2 * Hsz] = h1;
                if (!pf && write_states) {
                    size_t hb = (size_t)OUT_MAIN
                              + ((size_t)dir * Bsz + bb0) * Hsz + hg;
                    out[hb]       = h0;
                    out[hb + Hsz] = h1;
                    size_t cb = hb + 2 * (size_t)Bsz * Hsz;
                    out[cb]       = c0s;
                    out[cb + Hsz] = c1s;
                }
            }

            CWAIT();     // all CTAs' C[ph] reads done -> safe to push h[ph]

            if (pf && ge == ph) {
                uint16_t h0h, h0l, h1h, h1l;
                split_bf16(h0, h0h, h0l);
                split_bf16(h1, h1h, h1l);
                uint32_t phi = ((uint32_t)h1h << 16) | h0h;
                uint32_t plo = ((uint32_t)h1l << 16) | h0l;
                #pragma unroll
                for (int p = 0; p < CL; ++p) {
                    asm volatile("st.shared::cluster.b32 [%0],%1;"
                                 :: "r"(rHi[p]), "r"(phi) : "memory");
                    asm volatile("st.shared::cluster.b32 [%0],%1;"
                                 :: "r"(rHi[p] + CS), "r"(plo) : "memory");
                }
            }
            // pushes are released by the NEXT phase's arrive and acquired by
            // its wait before anyone re-reads this C region.
        }
    }
}

extern "C" void kernel_launch(void* const* d_in, const int* in_sizes, int n_in,
                              void* d_out, int out_size)
{
    const float* x  = (const float*)d_in[0];
    const float* Wf = (const float*)d_in[1];
    const float* bf = (const float*)d_in[2];
    const float* Wb = (const float*)d_in[3];
    const float* bb = (const float*)d_in[4];

    cudaFuncSetAttribute(bilstm_pipe,
                         cudaFuncAttributeMaxDynamicSharedMemorySize, SMEM_DYN);

    int ws = ((long long)out_size >= OUT_FULL) ? 1 : 0;
    bilstm_pipe<<<128, 256, SMEM_DYN>>>(x, Wf, bf, Wb, bb, (float*)d_out, ws);
}

// round 13
// speedup vs baseline: 2.4930x; 2.0330x over previous
#include <cuda_runtime.h>
#include <cuda_bf16.h>
#include <cstdint>

// ---------------------------------------------------------------------------
// BiLSTM B=128,S=1024,D=128,H=256 — R13: single-phase n=16 GEMM, gate-
// interleaved A tiles, fully in-register epilogue, zero intra-CTA barriers.
// Sync primitives restricted to the set proven in passing runs (R3/R9/R11):
// barrier.cluster.aligned, __syncthreads (init only), st.shared::cluster, mapa.
//
// concat[b,k] = x[k,t,b] (k<128) | h[b,k-128]   (source transpose quirk)
//
// 16 clusters x 8 CTAs (1 CTA/SM, 221184 B smem). CTA owns 32 hidden units
// (128 gate rows) of W as bf16 hi+lo packed ldmatrix tiles, GATE-INTERLEAVED:
// warp w -> hidden chunk hc=w>>1 (8 units), col half ch=w&1 (8 batches);
// tile0 = [f | i], tile1 = [c | o] rows for that chunk. After mma.sync
// m16n8k16 (3-term bf16 split, 6 independent 24-long chains), thread
// (lane) holds ALL FOUR gates for hidden 8hc+lane/4, batches 8ch+2(lane&3)+{0,1}
// in registers -> epilogue + h push without any shared staging.
// Per step: GEMM -> cluster(arrive a) -> reg epilogue + out stores ->
// wait(a) -> push h + stage x(t+1) -> cluster round (b). No __syncthreads.
// ---------------------------------------------------------------------------

namespace {
constexpr int Bsz = 128, Ssz = 1024, Dsz = 128, Hsz = 256, Ksz = 384;
constexpr int CL = 8;

constexpr uint32_t ATILE = 128 * 384 * 2;      // 98304 per W split (hi, lo)
constexpr uint32_t CB    = 2 * ATILE;          // 196608: concat tile base
constexpr uint32_t CSP   = 384 * 16 * 2;       // 12288 per concat split
constexpr int SMEM_DYN   = (int)(CB + 2 * CSP);  // 221184

constexpr long long OUT_MAIN = (long long)Bsz * Ssz * 2 * Hsz;
constexpr long long OUT_FULL = OUT_MAIN + 4LL * Bsz * Hsz;
}

__device__ __forceinline__ uint32_t smem_u32(const void* p) {
    uint32_t a;
    asm("{ .reg .u64 t; cvta.to.shared.u64 t, %1; cvt.u32.u64 %0, t; }"
        : "=r"(a) : "l"(p));
    return a;
}

// A packed-tile offset: packed row r in [0,128), col k in [0,384).
// tile t = r>>4 (512B per (t,kt)); inside: four 8x8 b16 matrices,
// m = (kk>>3)*2 + (rr>>3), each 128B row-major.
__device__ __forceinline__ uint32_t aoff(int r, int k) {
    uint32_t t = (uint32_t)(r >> 4), rr = (uint32_t)(r & 15);
    uint32_t kt = (uint32_t)(k >> 4), kk = (uint32_t)(k & 15);
    uint32_t m = ((kk >> 3) << 1) + (rr >> 3);
    return (t * 24u + kt) * 512u + m * 128u + (rr & 7u) * 16u + (kk & 7u) * 2u;
}
// C tile offset: per kt 512B = [colhalf0: k0-7 | k8-15][colhalf1: ...],
// each 8x8 b16 matrix 128B contiguous (conflict-free LDSM2T). b in [0,16).
__device__ __forceinline__ uint32_t coff(int k, int b) {
    uint32_t kt = (uint32_t)(k >> 4), kk = (uint32_t)(k & 15);
    return kt * 512u + (uint32_t)(b >> 3) * 256u + (kk >> 3) * 128u
         + (kk & 7u) * 16u + (uint32_t)(b & 7) * 2u;
}

__device__ __forceinline__ float sigm(float v) {
    return __fdividef(1.0f, 1.0f + __expf(-v));
}
__device__ __forceinline__ float tanhf_(float v) {
    return 1.0f - __fdividef(2.0f, __expf(2.0f * v) + 1.0f);
}

__device__ __forceinline__ void split_bf16(float v, uint16_t& hi, uint16_t& lo) {
    __nv_bfloat16 h = __float2bfloat16(v);
    __nv_bfloat16 l = __float2bfloat16(v - __bfloat162float(h));
    hi = __bfloat16_as_ushort(h);
    lo = __bfloat16_as_ushort(l);
}

#define LDSM4(r0,r1,r2,r3,addr) \
    asm volatile("ldmatrix.sync.aligned.m8n8.x4.shared.b16 {%0,%1,%2,%3},[%4];" \
        : "=r"(r0),"=r"(r1),"=r"(r2),"=r"(r3) : "r"(addr))
#define LDSM2T(r0,r1,addr) \
    asm volatile("ldmatrix.sync.aligned.m8n8.x2.trans.shared.b16 {%0,%1},[%2];" \
        : "=r"(r0),"=r"(r1) : "r"(addr))
#define MMA16816(d,a0,a1,a2,a3,b0,b1) \
    asm volatile("mma.sync.aligned.m16n8k16.row.col.f32.bf16.bf16.f32 " \
        "{%0,%1,%2,%3},{%4,%5,%6,%7},{%8,%9},{%0,%1,%2,%3};" \
        : "+f"((d)[0]),"+f"((d)[1]),"+f"((d)[2]),"+f"((d)[3]) \
        : "r"(a0),"r"(a1),"r"(a2),"r"(a3),"r"(b0),"r"(b1))
#define CARRIVE() asm volatile("barrier.cluster.arrive.aligned;" ::: "memory")
#define CWAIT()   asm volatile("barrier.cluster.wait.aligned;"   ::: "memory")

__global__ void __launch_bounds__(256, 1) __cluster_dims__(CL, 1, 1)
bilstm_reg(const float* __restrict__ x,
           const float* __restrict__ Wf, const float* __restrict__ bf,
           const float* __restrict__ Wb, const float* __restrict__ bb,
           float* __restrict__ out, int write_states)
{
    extern __shared__ char smc[];
    const uint32_t smb = smem_u32(smc);

    const int tid  = threadIdx.x;
    const int wid  = tid >> 5;
    const int lane = tid & 31;
    uint32_t myrank;
    asm("mov.u32 %0, %%cluster_ctarank;" : "=r"(myrank));
    const int rank = (int)myrank;
    const int cid  = blockIdx.x >> 3;
    const int dir  = cid >> 3;
    const int bg   = (cid & 7) * 16;

    const float* W    = dir ? Wb : Wf;
    const float* bias = dir ? bb : bf;

    // ---- W slice -> gate-interleaved packed bf16 hi/lo A tiles ----
    // source row r = g*32 + jl; packed row rp = (jl>>3)*32 + (g>>1)*16
    //                                        + (g&1)*8 + (jl&7)
    for (int idx = tid; idx < 128 * Ksz; idx += 256) {
        int r = idx / Ksz, k = idx - r * Ksz;
        int g = r >> 5, jl = r & 31;
        int rp = ((jl >> 3) << 5) + ((g >> 1) << 4) + ((g & 1) << 3) + (jl & 7);
        int gr = g * Hsz + rank * 32 + jl;
        float v = W[(size_t)gr * Ksz + k];
        uint16_t hi, lo; split_bf16(v, hi, lo);
        uint32_t o = aoff(rp, k);
        *(uint16_t*)(smc + o)         = hi;
        *(uint16_t*)(smc + ATILE + o) = lo;
    }
    // zero concat tiles (h(0) = 0)
    for (int i = tid; i < (int)(2 * CSP) / 4; i += 256)
        ((uint32_t*)(smc + CB))[i] = 0;
    __syncthreads();

    // ---- x staging: thread -> (k row kq = tid>>1, col half xh = tid&1) ----
    const int kq = tid >> 1, xh = tid & 1;
    const uint32_t xdst = CB + coff(kq, 8 * xh);   // 16B-aligned
    {
        int tt0 = dir ? (Ssz - 1) : 0;
        const float4* src = (const float4*)(x + (size_t)kq * Ssz * Dsz
                                              + (size_t)tt0 * Dsz + bg + 8 * xh);
        float4 v0 = src[0], v1 = src[1];
        uint16_t hi[8], lo[8];
        #pragma unroll
        for (int i = 0; i < 8; ++i) {
            float v = (i < 4) ? ((const float*)&v0)[i] : ((const float*)&v1)[i - 4];
            split_bf16(v, hi[i], lo[i]);
        }
        uint32_t wh[4], wl[4];
        #pragma unroll
        for (int i = 0; i < 4; ++i) {
            wh[i] = (uint32_t)hi[2*i] | ((uint32_t)hi[2*i+1] << 16);
            wl[i] = (uint32_t)lo[2*i] | ((uint32_t)lo[2*i+1] << 16);
        }
        *(uint4*)(smc + xdst)       = make_uint4(wh[0], wh[1], wh[2], wh[3]);
        *(uint4*)(smc + xdst + CSP) = make_uint4(wl[0], wl[1], wl[2], wl[3]);
    }

    // ---- per-thread ownership: hidden h, batch cols c0,c0+1 ----
    const int hc = wid >> 1;            // hidden chunk (8 units)
    const int ch = wid & 1;             // batch col half
    const int hh = 8 * hc + (lane >> 2);
    const int hg = rank * 32 + hh;
    const int c0 = 8 * ch + 2 * (lane & 3);
    const float bF = bias[0 * Hsz + hg], bI = bias[1 * Hsz + hg],
                bC = bias[2 * Hsz + hg], bO = bias[3 * Hsz + hg];

    // DSMEM push addresses: C[k=128+hg][c0..c0+1] hi split, in all 8 CTAs
    uint32_t rHi[CL];
    {
        uint32_t loc = smb + CB + coff(Dsz + hg, c0);
        #pragma unroll
        for (int p = 0; p < CL; ++p)
            asm("mapa.shared::cluster.u32 %0,%1,%2;" : "=r"(rHi[p]) : "r"(loc), "r"(p));
    }

    // GEMM bases: warp's tile-pair = 2*hc, col half ch
    const uint32_t a_lane = (uint32_t)(lane >> 3) * 128u + (uint32_t)(lane & 7) * 16u;
    const uint32_t aT0 = smb + (uint32_t)(wid & 6) * 12288u + a_lane; // (2hc)*24*512
    const uint32_t aT1 = aT0 + 12288u;
    const uint32_t bB  = smb + CB + (uint32_t)ch * 256u + (uint32_t)(lane & 15) * 16u;

    float c0s = 0.f, c1s = 0.f;

    __syncthreads();
    CARRIVE(); CWAIT();     // initial staging visible cluster-wide

    for (int step = 0; step < Ssz; ++step) {
        const int  tt = dir ? (Ssz - 1 - step) : step;
        const bool pf = (step + 1 < Ssz);

        // prefetch next x into registers
        float4 p0, p1;
        if (pf) {
            const int ttn = dir ? (tt - 1) : (tt + 1);
            const float4* src = (const float4*)(x + (size_t)kq * Ssz * Dsz
                                                  + (size_t)ttn * Dsz + bg + 8 * xh);
            p0 = src[0]; p1 = src[1];
        }

        // ---- GEMM: 2 gate-tiles x 24 kt x 3 split terms, n=8 ----
        float t0HH[4] = {0,0,0,0}, t0HL[4] = {0,0,0,0}, t0LH[4] = {0,0,0,0};
        float t1HH[4] = {0,0,0,0}, t1HL[4] = {0,0,0,0}, t1LH[4] = {0,0,0,0};
        #pragma unroll
        for (int kt = 0; kt < 24; ++kt) {
            uint32_t f0,f1,f2,f3, g0,g1,g2,g3;       // tile0 hi, tile0 lo
            uint32_t q0,q1,q2,q3, r0,r1,r2,r3;       // tile1 hi, tile1 lo
            uint32_t bh0,bh1, bl0,bl1;
            uint32_t a0 = aT0 + (uint32_t)kt * 512u;
            uint32_t a1 = aT1 + (uint32_t)kt * 512u;
            uint32_t bd = bB  + (uint32_t)kt * 512u;
            LDSM4(f0,f1,f2,f3, a0);
            LDSM4(g0,g1,g2,g3, a0 + ATILE);
            LDSM4(q0,q1,q2,q3, a1);
            LDSM4(r0,r1,r2,r3, a1 + ATILE);
            LDSM2T(bh0,bh1, bd);
            LDSM2T(bl0,bl1, bd + CSP);
            MMA16816(t0HH, f0,f1,f2,f3, bh0,bh1);
            MMA16816(t1HH, q0,q1,q2,q3, bh0,bh1);
            MMA16816(t0HL, f0,f1,f2,f3, bl0,bl1);
            MMA16816(t1HL, q0,q1,q2,q3, bl0,bl1);
            MMA16816(t0LH, g0,g1,g2,g3, bh0,bh1);
            MMA16816(t1LH, r0,r1,r2,r3, bh0,bh1);
        }

        CARRIVE();   // (a) my reads of C are done

        // ---- in-register epilogue: all 4 gates live in this thread ----
        float zF0 = t0HH[0] + t0HL[0] + t0LH[0];
        float zF1 = t0HH[1] + t0HL[1] + t0LH[1];
        float zI0 = t0HH[2] + t0HL[2] + t0LH[2];
        float zI1 = t0HH[3] + t0HL[3] + t0LH[3];
        float zC0 = t1HH[0] + t1HL[0] + t1LH[0];
        float zC1 = t1HH[1] + t1HL[1] + t1LH[1];
        float zO0 = t1HH[2] + t1HL[2] + t1LH[2];
        float zO1 = t1HH[3] + t1HL[3] + t1LH[3];

        float f0s = sigm(zF0 + bF),   f1s = sigm(zF1 + bF);
        float i0s = sigm(zI0 + bI),   i1s = sigm(zI1 + bI);
        float g0s = tanhf_(zC0 + bC), g1s = tanhf_(zC1 + bC);
        float o0s = sigm(zO0 + bO),   o1s = sigm(zO1 + bO);

        c0s = f0s * c0s + i0s * g0s;
        c1s = f1s * c1s + i1s * g1s;
        float h0 = o0s * tanhf_(c0s);
        float h1 = o1s * tanhf_(c1s);

        // out[bg+c0(+1), tt, dir*H + hg]  (hides part of the wait)
        {
            size_t ob = ((size_t)(bg + c0) * Ssz + (size_t)tt) * (2 * Hsz)
                      + (size_t)dir * Hsz + hg;
            out[ob]                         = h0;
            out[ob + (size_t)Ssz * 2 * Hsz] = h1;
            if (!pf && write_states) {
                size_t hb = (size_t)OUT_MAIN
                          + ((size_t)dir * Bsz + bg + c0) * Hsz + hg;
                out[hb]       = h0;
                out[hb + Hsz] = h1;
                size_t cb = hb + 2 * (size_t)Bsz * Hsz;
                out[cb]       = c0s;
                out[cb + Hsz] = c1s;
            }
        }

        CWAIT();     // (a) all CTAs' reads done -> safe to overwrite C

        if (pf) {
            // push h pair to all 8 CTAs (hi + lo splits)
            uint16_t h0h, h0l, h1h, h1l;
            split_bf16(h0, h0h, h0l);
            split_bf16(h1, h1h, h1l);
            uint32_t phi = ((uint32_t)h1h << 16) | h0h;
            uint32_t plo = ((uint32_t)h1l << 16) | h0l;
            #pragma unroll
            for (int p = 0; p < CL; ++p) {
                asm volatile("st.shared::cluster.b32 [%0],%1;"
                             :: "r"(rHi[p]), "r"(phi) : "memory");
                asm volatile("st.shared::cluster.b32 [%0],%1;"
                             :: "r"(rHi[p] + CSP), "r"(plo) : "memory");
            }
            // stage x(t+1) into own C
            {
                uint16_t hi[8], lo[8];
                #pragma unroll
                for (int i = 0; i < 8; ++i) {
                    float v = (i < 4) ? ((const float*)&p0)[i]
                                      : ((const float*)&p1)[i - 4];
                    split_bf16(v, hi[i], lo[i]);
                }
                uint32_t wh[4], wl[4];
                #pragma unroll
                for (int i = 0; i < 4; ++i) {
                    wh[i] = (uint32_t)hi[2*i] | ((uint32_t)hi[2*i+1] << 16);
                    wl[i] = (uint32_t)lo[2*i] | ((uint32_t)lo[2*i+1] << 16);
                }
                *(uint4*)(smc + xdst)       = make_uint4(wh[0], wh[1], wh[2], wh[3]);
                *(uint4*)(smc + xdst + CSP) = make_uint4(wl[0], wl[1], wl[2], wl[3]);
            }
            // (b) all writes posted -> visible before next GEMM
            CARRIVE(); CWAIT();
        }
    }

    // keep cluster alive until everyone is done touching DSMEM
    CARRIVE(); CWAIT();
}

extern "C" void kernel_launch(void* const* d_in, const int* in_sizes, int n_in,
                              void* d_out, int out_size)
{
    const float* x  = (const float*)d_in[0];
    const float* Wf = (const float*)d_in[1];
    const float* bf = (const float*)d_in[2];
    const float* Wb = (const float*)d_in[3];
    const float* bb = (const float*)d_in[4];

    cudaFuncSetAttribute(bilstm_reg,
                         cudaFuncAttributeMaxDynamicSharedMemorySize, SMEM_DYN);

    int ws = ((long long)out_size >= OUT_FULL) ? 1 : 0;
    bilstm_reg<<<128, 256, SMEM_DYN>>>(x, Wf, bf, Wb, bb, (float*)d_out, ws);
}

// round 14
// speedup vs baseline: 3.1548x; 1.2654x over previous
#include <cuda_runtime.h>
#include <cuda_bf16.h>
#include <cuda_fp16.h>
#include <cstdint>

// ---------------------------------------------------------------------------
// BiLSTM B=128,S=1024,D=128,H=256 — R14: double-buffered concat, ONE cluster
// round per step, fp16 single-term x-path + bf16 3-term h-path.
//
// concat[b,k] = x[k,t,b] (k<128) | h[b,k-128]   (source transpose quirk)
//
// 16 clusters x 8 CTAs (1 CTA/SM, 204800 B smem). CTA owns 32 hidden units
// (128 gate rows) of W, gate-interleaved packed ldmatrix tiles:
//   A_hi: kt 0..7 (x cols) stored FP16, kt 8..23 (h cols) BF16-hi.
//   A_lo: h cols only (kt 8..23), BF16-lo.
// Concat C is PING-PONG buffered (buf[t&1] read at step t; h(t+1) pushed and
// x(t+1) staged into buf[(t+1)&1]). Per buffer: x fp16 (4K) + h hi (8K) +
// h lo (8K). Hazard-free by construction -> exactly one cluster
// arrive/wait per step, with global out-stores between arrive and wait.
// GEMM per warp: 8 x-kt (1 f16 MMA x 2 tiles) + 16 h-kt (3-term bf16,
// 6 MMAs) = 112 MMAs, 6 independent accumulator chains. In-register epilogue
// (thread holds all 4 gates for one hidden unit x 2 batches).
// Sync primitives: only the proven set (barrier.cluster.aligned,
// st.shared::cluster, mapa). No mbarriers, no loop __syncthreads.
// ---------------------------------------------------------------------------

namespace {
constexpr int Bsz = 128, Ssz = 1024, Dsz = 128, Hsz = 256, Ksz = 384;
constexpr int CL = 8;

constexpr uint32_t AHI   = 0;                  // 128 x 384 x 2B (fp16/bf16 mix)
constexpr uint32_t AHISZ = 128 * 384 * 2;      // 98304
constexpr uint32_t ALO   = AHISZ;              // 128 x 256 x 2B (h cols bf16-lo)
constexpr uint32_t ALOSZ = 128 * 256 * 2;      // 65536
constexpr uint32_t CB    = AHI + AHISZ + ALOSZ;  // 163840
// per-buffer layout: [x fp16: 8kt*512=4096][h hi: 16kt*512=8192][h lo: 8192]
constexpr uint32_t CXO   = 0;
constexpr uint32_t CHH   = 4096;
constexpr uint32_t CHL   = 12288;
constexpr uint32_t CBUF  = 20480;
constexpr int SMEM_DYN   = (int)(CB + 2 * CBUF);   // 204800

constexpr long long OUT_MAIN = (long long)Bsz * Ssz * 2 * Hsz;
constexpr long long OUT_FULL = OUT_MAIN + 4LL * Bsz * Hsz;
}

__device__ __forceinline__ uint32_t smem_u32(const void* p) {
    uint32_t a;
    asm("{ .reg .u64 t; cvta.to.shared.u64 t, %1; cvt.u32.u64 %0, t; }"
        : "=r"(a) : "l"(p));
    return a;
}

// A packed-tile offset: packed row r in [0,128), col-tile kt, col-in-tile kk.
// tile t = r>>4; per (t,kt) 512B: four 8x8 b16 matrices, m=(kk>>3)*2+(rr>>3).
__device__ __forceinline__ uint32_t aoff_g(int r, int kt, int kk, int ktn) {
    uint32_t t = (uint32_t)(r >> 4), rr = (uint32_t)(r & 15);
    uint32_t m = (((uint32_t)kk >> 3) << 1) + (rr >> 3);
    return (t * (uint32_t)ktn + (uint32_t)kt) * 512u + m * 128u
         + (rr & 7u) * 16u + ((uint32_t)kk & 7u) * 2u;
}
// C tile offset within a region: row k in [0,R), col b in [0,16).
__device__ __forceinline__ uint32_t coff(int k, int b) {
    uint32_t kt = (uint32_t)(k >> 4), kk = (uint32_t)(k & 15);
    return kt * 512u + (uint32_t)(b >> 3) * 256u + (kk >> 3) * 128u
         + (kk & 7u) * 16u + (uint32_t)(b & 7) * 2u;
}

__device__ __forceinline__ float sigm(float v) {
    return __fdividef(1.0f, 1.0f + __expf(-v));
}
__device__ __forceinline__ float tanhf_(float v) {
    return 1.0f - __fdividef(2.0f, __expf(2.0f * v) + 1.0f);
}

__device__ __forceinline__ void split_bf16(float v, uint16_t& hi, uint16_t& lo) {
    __nv_bfloat16 h = __float2bfloat16(v);
    __nv_bfloat16 l = __float2bfloat16(v - __bfloat162float(h));
    hi = __bfloat16_as_ushort(h);
    lo = __bfloat16_as_ushort(l);
}

#define LDSM4(r0,r1,r2,r3,addr) \
    asm volatile("ldmatrix.sync.aligned.m8n8.x4.shared.b16 {%0,%1,%2,%3},[%4];" \
        : "=r"(r0),"=r"(r1),"=r"(r2),"=r"(r3) : "r"(addr))
#define LDSM2T(r0,r1,addr) \
    asm volatile("ldmatrix.sync.aligned.m8n8.x2.trans.shared.b16 {%0,%1},[%2];" \
        : "=r"(r0),"=r"(r1) : "r"(addr))
#define MMABF(d,a0,a1,a2,a3,b0,b1) \
    asm volatile("mma.sync.aligned.m16n8k16.row.col.f32.bf16.bf16.f32 " \
        "{%0,%1,%2,%3},{%4,%5,%6,%7},{%8,%9},{%0,%1,%2,%3};" \
        : "+f"((d)[0]),"+f"((d)[1]),"+f"((d)[2]),"+f"((d)[3]) \
        : "r"(a0),"r"(a1),"r"(a2),"r"(a3),"r"(b0),"r"(b1))
#define MMAF16(d,a0,a1,a2,a3,b0,b1) \
    asm volatile("mma.sync.aligned.m16n8k16.row.col.f32.f16.f16.f32 " \
        "{%0,%1,%2,%3},{%4,%5,%6,%7},{%8,%9},{%0,%1,%2,%3};" \
        : "+f"((d)[0]),"+f"((d)[1]),"+f"((d)[2]),"+f"((d)[3]) \
        : "r"(a0),"r"(a1),"r"(a2),"r"(a3),"r"(b0),"r"(b1))
#define CARRIVE() asm volatile("barrier.cluster.arrive.aligned;" ::: "memory")
#define CWAIT()   asm volatile("barrier.cluster.wait.aligned;"   ::: "memory")

__global__ void __launch_bounds__(256, 1) __cluster_dims__(CL, 1, 1)
bilstm_db(const float* __restrict__ x,
          const float* __restrict__ Wf, const float* __restrict__ bf,
          const float* __restrict__ Wb, const float* __restrict__ bb,
          float* __restrict__ out, int write_states)
{
    extern __shared__ char smc[];
    const uint32_t smb = smem_u32(smc);

    const int tid  = threadIdx.x;
    const int wid  = tid >> 5;
    const int lane = tid & 31;
    uint32_t myrank;
    asm("mov.u32 %0, %%cluster_ctarank;" : "=r"(myrank));
    const int rank = (int)myrank;
    const int cid  = blockIdx.x >> 3;
    const int dir  = cid >> 3;
    const int bg   = (cid & 7) * 16;

    const float* W    = dir ? Wb : Wf;
    const float* bias = dir ? bb : bf;

    // ---- W slice -> gate-interleaved packed A tiles ----
    // source row r = g*32 + jl; packed row rp = (jl>>3)*32+(g>>1)*16+(g&1)*8+(jl&7)
    for (int idx = tid; idx < 128 * Ksz; idx += 256) {
        int r = idx / Ksz, k = idx - r * Ksz;
        int g = r >> 5, jl = r & 31;
        int rp = ((jl >> 3) << 5) + ((g >> 1) << 4) + ((g & 1) << 3) + (jl & 7);
        int gr = g * Hsz + rank * 32 + jl;
        float v = W[(size_t)gr * Ksz + k];
        if (k < Dsz) {
            // x columns: fp16 single-term
            uint16_t hv = __half_as_ushort(__float2half(v));
            *(uint16_t*)(smc + AHI + aoff_g(rp, k >> 4, k & 15, 24)) = hv;
        } else {
            // h columns: bf16 hi + lo
            uint16_t hi, lo; split_bf16(v, hi, lo);
            int kh = k - Dsz;
            *(uint16_t*)(smc + AHI + aoff_g(rp, 8 + (kh >> 4), kh & 15, 24)) = hi;
            *(uint16_t*)(smc + ALO + aoff_g(rp, kh >> 4, kh & 15, 16)) = lo;
        }
    }
    // zero both C buffers (h(0) = 0; x region overwritten below)
    for (int i = tid; i < (int)(2 * CBUF) / 4; i += 256)
        ((uint32_t*)(smc + CB))[i] = 0;
    __syncthreads();

    // ---- x staging: thread -> (k row kq = tid>>1, col half xh = tid&1) ----
    const int kq = tid >> 1, xh = tid & 1;
    const uint32_t xdst = CB + CXO + coff(kq, 8 * xh);   // + buffer offset
    {
        int tt0 = dir ? (Ssz - 1) : 0;
        const float4* src = (const float4*)(x + (size_t)kq * Ssz * Dsz
                                              + (size_t)tt0 * Dsz + bg + 8 * xh);
        float4 v0 = src[0], v1 = src[1];
        uint32_t wv[4];
        #pragma unroll
        for (int i = 0; i < 4; ++i) {
            float a = (i < 2) ? ((const float*)&v0)[2*i]   : ((const float*)&v1)[2*i-4];
            float b = (i < 2) ? ((const float*)&v0)[2*i+1] : ((const float*)&v1)[2*i-3];
            __half2 hp = __floats2half2_rn(a, b);
            wv[i] = *(uint32_t*)&hp;
        }
        *(uint4*)(smc + xdst) = make_uint4(wv[0], wv[1], wv[2], wv[3]);  // buf 0
    }

    // ---- per-thread ownership: hidden hh, batch cols c0,c0+1 ----
    const int hc = wid >> 1;            // hidden chunk (8 units)
    const int ch = wid & 1;             // batch col half
    const int hh = 8 * hc + (lane >> 2);
    const int hg = rank * 32 + hh;
    const int c0 = 8 * ch + 2 * (lane & 3);
    const float bF = bias[0 * Hsz + hg], bI = bias[1 * Hsz + hg],
                bC = bias[2 * Hsz + hg], bO = bias[3 * Hsz + hg];

    // DSMEM push addresses (buffer 0): h-hi at CHH + coff(hg, c0); lo at +8192
    uint32_t rHi[CL];
    {
        uint32_t loc = smb + CB + CHH + coff(hg, c0);
        #pragma unroll
        for (int p = 0; p < CL; ++p)
            asm("mapa.shared::cluster.u32 %0,%1,%2;" : "=r"(rHi[p]) : "r"(loc), "r"(p));
    }

    // GEMM per-lane bases
    const uint32_t a_lane = (uint32_t)(lane >> 3) * 128u + (uint32_t)(lane & 7) * 16u;
    const uint32_t aT0 = smb + AHI + (uint32_t)(wid & 6) * 12288u + a_lane;  // 24kt
    const uint32_t aT1 = aT0 + 12288u;
    const uint32_t aL0 = smb + ALO + (uint32_t)(wid & 6) * 8192u + a_lane;   // 16kt
    const uint32_t aL1 = aL0 + 8192u;
    const uint32_t b_lane = (uint32_t)ch * 256u + (uint32_t)(lane & 15) * 16u;

    float c0s = 0.f, c1s = 0.f;

    __syncthreads();
    CARRIVE(); CWAIT();     // initial staging + zeros visible cluster-wide

    for (int step = 0; step < Ssz; ++step) {
        const int  tt = dir ? (Ssz - 1 - step) : step;
        const bool pf = (step + 1 < Ssz);
        const uint32_t rdo = (step & 1) ? CBUF : 0u;   // read-buffer offset
        const uint32_t wro = CBUF - rdo;               // write-buffer offset

        // prefetch next x into registers
        float4 p0, p1;
        if (pf) {
            const int ttn = dir ? (tt - 1) : (tt + 1);
            const float4* src = (const float4*)(x + (size_t)kq * Ssz * Dsz
                                                  + (size_t)ttn * Dsz + bg + 8 * xh);
            p0 = src[0]; p1 = src[1];
        }

        const uint32_t cbx = smb + CB + rdo + CXO + b_lane;
        const uint32_t cbh = smb + CB + rdo + CHH + b_lane;

        // ---- GEMM: 8 x-kt (fp16, 1 term) + 16 h-kt (bf16, 3 terms) ----
        float t0HH[4] = {0,0,0,0}, t0HL[4] = {0,0,0,0}, t0LH[4] = {0,0,0,0};
        float t1HH[4] = {0,0,0,0}, t1HL[4] = {0,0,0,0}, t1LH[4] = {0,0,0,0};
        #pragma unroll
        for (int kt = 0; kt < 8; ++kt) {
            uint32_t f0,f1,f2,f3, q0,q1,q2,q3, bx0,bx1;
            uint32_t a0 = aT0 + (uint32_t)kt * 512u;
            uint32_t a1 = aT1 + (uint32_t)kt * 512u;
            LDSM4(f0,f1,f2,f3, a0);
            LDSM4(q0,q1,q2,q3, a1);
            LDSM2T(bx0,bx1, cbx + (uint32_t)kt * 512u);
            MMAF16(t0HH, f0,f1,f2,f3, bx0,bx1);
            MMAF16(t1HH, q0,q1,q2,q3, bx0,bx1);
        }
        #pragma unroll
        for (int kt = 0; kt < 16; ++kt) {
            uint32_t f0,f1,f2,f3, g0,g1,g2,g3;
            uint32_t q0,q1,q2,q3, r0,r1,r2,r3;
            uint32_t bh0,bh1, bl0,bl1;
            uint32_t a0 = aT0 + (uint32_t)(8 + kt) * 512u;
            uint32_t a1 = aT1 + (uint32_t)(8 + kt) * 512u;
            uint32_t l0 = aL0 + (uint32_t)kt * 512u;
            uint32_t l1 = aL1 + (uint32_t)kt * 512u;
            uint32_t bd = cbh + (uint32_t)kt * 512u;
            LDSM4(f0,f1,f2,f3, a0);
            LDSM4(g0,g1,g2,g3, l0);
            LDSM4(q0,q1,q2,q3, a1);
            LDSM4(r0,r1,r2,r3, l1);
            LDSM2T(bh0,bh1, bd);
            LDSM2T(bl0,bl1, bd + 8192u);
            MMABF(t0HH, f0,f1,f2,f3, bh0,bh1);
            MMABF(t1HH, q0,q1,q2,q3, bh0,bh1);
            MMABF(t0HL, f0,f1,f2,f3, bl0,bl1);
            MMABF(t1HL, q0,q1,q2,q3, bl0,bl1);
            MMABF(t0LH, g0,g1,g2,g3, bh0,bh1);
            MMABF(t1LH, r0,r1,r2,r3, bh0,bh1);
        }

        // ---- in-register epilogue ----
        float zF0 = t0HH[0] + t0HL[0] + t0LH[0];
        float zF1 = t0HH[1] + t0HL[1] + t0LH[1];
        float zI0 = t0HH[2] + t0HL[2] + t0LH[2];
        float zI1 = t0HH[3] + t0HL[3] + t0LH[3];
        float zC0 = t1HH[0] + t1HL[0] + t1LH[0];
        float zC1 = t1HH[1] + t1HL[1] + t1LH[1];
        float zO0 = t1HH[2] + t1HL[2] + t1LH[2];
        float zO1 = t1HH[3] + t1HL[3] + t1LH[3];

        float f0s = sigm(zF0 + bF),   f1s = sigm(zF1 + bF);
        float i0s = sigm(zI0 + bI),   i1s = sigm(zI1 + bI);
        float g0s = tanhf_(zC0 + bC), g1s = tanhf_(zC1 + bC);
        float o0s = sigm(zO0 + bO),   o1s = sigm(zO1 + bO);

        c0s = f0s * c0s + i0s * g0s;
        c1s = f1s * c1s + i1s * g1s;
        float h0 = o0s * tanhf_(c0s);
        float h1 = o1s * tanhf_(c1s);

        if (pf) {
            // push h pair into ALL 8 CTAs' WRITE buffer (hi + lo)
            uint16_t h0h, h0l, h1h, h1l;
            split_bf16(h0, h0h, h0l);
            split_bf16(h1, h1h, h1l);
            uint32_t phi = ((uint32_t)h1h << 16) | h0h;
            uint32_t plo = ((uint32_t)h1l << 16) | h0l;
            #pragma unroll
            for (int p = 0; p < CL; ++p) {
                uint32_t dst = rHi[p] + wro;
                asm volatile("st.shared::cluster.b32 [%0],%1;"
                             :: "r"(dst), "r"(phi) : "memory");
                asm volatile("st.shared::cluster.b32 [%0],%1;"
                             :: "r"(dst + 8192u), "r"(plo) : "memory");
            }
            // stage x(t+1) fp16 into own WRITE buffer
            uint32_t wv[4];
            #pragma unroll
            for (int i = 0; i < 4; ++i) {
                float a = (i < 2) ? ((const float*)&p0)[2*i]   : ((const float*)&p1)[2*i-4];
                float b = (i < 2) ? ((const float*)&p0)[2*i+1] : ((const float*)&p1)[2*i-3];
                __half2 hp = __floats2half2_rn(a, b);
                wv[i] = *(uint32_t*)&hp;
            }
            *(uint4*)(smc + xdst + wro) = make_uint4(wv[0], wv[1], wv[2], wv[3]);
        }

        // single cluster round; out-stores hide the propagation
        CARRIVE();
        {
            size_t ob = ((size_t)(bg + c0) * Ssz + (size_t)tt) * (2 * Hsz)
                      + (size_t)dir * Hsz + hg;
            out[ob]                         = h0;
            out[ob + (size_t)Ssz * 2 * Hsz] = h1;
            if (!pf && write_states) {
                size_t hb = (size_t)OUT_MAIN
                          + ((size_t)dir * Bsz + bg + c0) * Hsz + hg;
                out[hb]       = h0;
                out[hb + Hsz] = h1;
                size_t cb2 = hb + 2 * (size_t)Bsz * Hsz;
                out[cb2]       = c0s;
                out[cb2 + Hsz] = c1s;
            }
        }
        CWAIT();
    }

    // keep cluster alive until everyone is done touching DSMEM
    CARRIVE(); CWAIT();
}

extern "C" void kernel_launch(void* const* d_in, const int* in_sizes, int n_in,
                              void* d_out, int out_size)
{
    const float* x  = (const float*)d_in[0];
    const float* Wf = (const float*)d_in[1];
    const float* bf = (const float*)d_in[2];
    const float* Wb = (const float*)d_in[3];
    const float* bb = (const float*)d_in[4];

    cudaFuncSetAttribute(bilstm_db,
                         cudaFuncAttributeMaxDynamicSharedMemorySize, SMEM_DYN);

    int ws = ((long long)out_size >= OUT_FULL) ? 1 : 0;
    bilstm_db<<<128, 256, SMEM_DYN>>>(x, Wf, bf, Wb, bb, (float*)d_out, ws);
}

// round 16
// speedup vs baseline: 3.2977x; 1.0453x over previous
#include <cuda_runtime.h>
#include <cuda_bf16.h>
#include <cuda_fp16.h>
#include <cstdint>

// ---------------------------------------------------------------------------
// BiLSTM B=128,S=1024,D=128,H=256 — R15: uniform fp16 2-term W x fp16
// single-term concat; halved DSMEM push; one cluster round per step.
//
// concat[b,k] = x[k,t,b] (k<128) | h[b,k-128]   (source transpose quirk)
//
// 16 clusters x 8 CTAs (1 CTA/SM, 221184 B smem). CTA owns 32 hidden units
// (128 gate rows) of W, gate-interleaved packed ldmatrix tiles, stored as
// fp16 hi + fp16 lo (W residual err ~1e-6). Concat C is fp16 single-term,
// PING-PONG buffered (24 kt x 512 B per buffer: kt 0..7 = x, 8..23 = h).
// Per step per warp: 24 kt x (4 LDSM4 + 1 LDSM2T + 4 MMAF16), 4 accumulator
// chains; in-register epilogue (thread holds all 4 gates for one hidden unit
// x 2 batches); h pushed as ONE fp16x2 b32 per peer CTA. One cluster
// arrive/wait per step with the global out-stores inside the window.
// Sync primitives: proven set only (barrier.cluster.aligned,
// st.shared::cluster, mapa). No mbarriers, no loop __syncthreads.
// ---------------------------------------------------------------------------

namespace {
constexpr int Bsz = 128, Ssz = 1024, Dsz = 128, Hsz = 256, Ksz = 384;
constexpr int CL = 8;

constexpr uint32_t AHI   = 0;                    // W hi: 128 x 384 fp16 packed
constexpr uint32_t ASZ   = 128 * 384 * 2;        // 98304 per split
constexpr uint32_t ALO   = ASZ;                  // W lo
constexpr uint32_t CB    = 2 * ASZ;              // 196608: concat buffers
constexpr uint32_t CBUF  = 24 * 512;             // 12288 per buffer
constexpr int SMEM_DYN   = (int)(CB + 2 * CBUF); // 221184

constexpr long long OUT_MAIN = (long long)Bsz * Ssz * 2 * Hsz;
constexpr long long OUT_FULL = OUT_MAIN + 4LL * Bsz * Hsz;
}

__device__ __forceinline__ uint32_t smem_u32(const void* p) {
    uint32_t a;
    asm("{ .reg .u64 t; cvta.to.shared.u64 t, %1; cvt.u32.u64 %0, t; }"
        : "=r"(a) : "l"(p));
    return a;
}

// A packed-tile offset: packed row r in [0,128), col-tile kt in [0,24),
// col kk in [0,16). tile t = r>>4; per (t,kt) 512B: four 8x8 b16 matrices,
// m = (kk>>3)*2 + (rr>>3).
__device__ __forceinline__ uint32_t aoff_g(int r, int kt, int kk) {
    uint32_t t = (uint32_t)(r >> 4), rr = (uint32_t)(r & 15);
    uint32_t m = (((uint32_t)kk >> 3) << 1) + (rr >> 3);
    return (t * 24u + (uint32_t)kt) * 512u + m * 128u
         + (rr & 7u) * 16u + ((uint32_t)kk & 7u) * 2u;
}
// C offset within a buffer: row k in [0,384), col b in [0,16).
__device__ __forceinline__ uint32_t coff(int k, int b) {
    uint32_t kt = (uint32_t)(k >> 4), kk = (uint32_t)(k & 15);
    return kt * 512u + (uint32_t)(b >> 3) * 256u + (kk >> 3) * 128u
         + (kk & 7u) * 16u + (uint32_t)(b & 7) * 2u;
}

__device__ __forceinline__ float sigm(float v) {
    return __fdividef(1.0f, 1.0f + __expf(-v));
}
__device__ __forceinline__ float tanhf_(float v) {
    return 1.0f - __fdividef(2.0f, __expf(2.0f * v) + 1.0f);
}

__device__ __forceinline__ void split_f16(float v, uint16_t& hi, uint16_t& lo) {
    __half h = __float2half(v);
    __half l = __float2half(v - __half2float(h));
    hi = __half_as_ushort(h);
    lo = __half_as_ushort(l);
}

#define LDSM4(r0,r1,r2,r3,addr) \
    asm volatile("ldmatrix.sync.aligned.m8n8.x4.shared.b16 {%0,%1,%2,%3},[%4];" \
        : "=r"(r0),"=r"(r1),"=r"(r2),"=r"(r3) : "r"(addr))
#define LDSM2T(r0,r1,addr) \
    asm volatile("ldmatrix.sync.aligned.m8n8.x2.trans.shared.b16 {%0,%1},[%2];" \
        : "=r"(r0),"=r"(r1) : "r"(addr))
#define MMAF16(d,a0,a1,a2,a3,b0,b1) \
    asm volatile("mma.sync.aligned.m16n8k16.row.col.f32.f16.f16.f32 " \
        "{%0,%1,%2,%3},{%4,%5,%6,%7},{%8,%9},{%0,%1,%2,%3};" \
        : "+f"((d)[0]),"+f"((d)[1]),"+f"((d)[2]),"+f"((d)[3]) \
        : "r"(a0),"r"(a1),"r"(a2),"r"(a3),"r"(b0),"r"(b1))
#define CARRIVE() asm volatile("barrier.cluster.arrive.aligned;" ::: "memory")
#define CWAIT()   asm volatile("barrier.cluster.wait.aligned;"   ::: "memory")

__global__ void __launch_bounds__(256, 1) __cluster_dims__(CL, 1, 1)
bilstm_u16(const float* __restrict__ x,
           const float* __restrict__ Wf, const float* __restrict__ bf,
           const float* __restrict__ Wb, const float* __restrict__ bb,
           float* __restrict__ out, int write_states)
{
    extern __shared__ char smc[];
    const uint32_t smb = smem_u32(smc);

    const int tid  = threadIdx.x;
    const int wid  = tid >> 5;
    const int lane = tid & 31;
    uint32_t myrank;
    asm("mov.u32 %0, %%cluster_ctarank;" : "=r"(myrank));
    const int rank = (int)myrank;
    const int cid  = blockIdx.x >> 3;
    const int dir  = cid >> 3;
    const int bg   = (cid & 7) * 16;

    const float* W    = dir ? Wb : Wf;
    const float* bias = dir ? bb : bf;

    // ---- W slice -> gate-interleaved packed fp16 hi/lo A tiles ----
    // source row r = g*32 + jl; packed rp = (jl>>3)*32+(g>>1)*16+(g&1)*8+(jl&7)
    for (int idx = tid; idx < 128 * Ksz; idx += 256) {
        int r = idx / Ksz, k = idx - r * Ksz;
        int g = r >> 5, jl = r & 31;
        int rp = ((jl >> 3) << 5) + ((g >> 1) << 4) + ((g & 1) << 3) + (jl & 7);
        int gr = g * Hsz + rank * 32 + jl;
        float v = W[(size_t)gr * Ksz + k];
        uint16_t hi, lo; split_f16(v, hi, lo);
        uint32_t o = aoff_g(rp, k >> 4, k & 15);
        *(uint16_t*)(smc + AHI + o) = hi;
        *(uint16_t*)(smc + ALO + o) = lo;
    }
    // zero both concat buffers (h(0) = 0)
    for (int i = tid; i < (int)(2 * CBUF) / 4; i += 256)
        ((uint32_t*)(smc + CB))[i] = 0;
    __syncthreads();

    // ---- x staging: thread -> (k row kq = tid>>1, col half xh = tid&1) ----
    const int kq = tid >> 1, xh = tid & 1;
    const uint32_t xdst = CB + coff(kq, 8 * xh);   // + buffer offset
    {
        int tt0 = dir ? (Ssz - 1) : 0;
        const float4* src = (const float4*)(x + (size_t)kq * Ssz * Dsz
                                              + (size_t)tt0 * Dsz + bg + 8 * xh);
        float4 v0 = src[0], v1 = src[1];
        uint32_t wv[4];
        #pragma unroll
        for (int i = 0; i < 4; ++i) {
            float a = (i < 2) ? ((const float*)&v0)[2*i]   : ((const float*)&v1)[2*i-4];
            float b = (i < 2) ? ((const float*)&v0)[2*i+1] : ((const float*)&v1)[2*i-3];
            __half2 hp = __floats2half2_rn(a, b);
            wv[i] = *(uint32_t*)&hp;
        }
        *(uint4*)(smc + xdst) = make_uint4(wv[0], wv[1], wv[2], wv[3]);  // buf 0
    }

    // ---- per-thread ownership: hidden hh, batch cols c0,c0+1 ----
    const int hc = wid >> 1;            // hidden chunk (8 units)
    const int ch = wid & 1;             // batch col half
    const int hh = 8 * hc + (lane >> 2);
    const int hg = rank * 32 + hh;
    const int c0 = 8 * ch + 2 * (lane & 3);
    const float bF = bias[0 * Hsz + hg], bI = bias[1 * Hsz + hg],
                bC = bias[2 * Hsz + hg], bO = bias[3 * Hsz + hg];

    // DSMEM push addresses (buffer 0): h at coff(128+hg, c0)
    uint32_t rHi[CL];
    {
        uint32_t loc = smb + CB + coff(Dsz + hg, c0);
        #pragma unroll
        for (int p = 0; p < CL; ++p)
            asm("mapa.shared::cluster.u32 %0,%1,%2;" : "=r"(rHi[p]) : "r"(loc), "r"(p));
    }

    // GEMM per-lane bases
    const uint32_t a_lane = (uint32_t)(lane >> 3) * 128u + (uint32_t)(lane & 7) * 16u;
    const uint32_t aH0 = smb + AHI + (uint32_t)(wid & 6) * 12288u + a_lane;
    const uint32_t aH1 = aH0 + 12288u;
    const uint32_t b_lane = (uint32_t)ch * 256u + (uint32_t)(lane & 15) * 16u;

    float c0s = 0.f, c1s = 0.f;

    __syncthreads();
    CARRIVE(); CWAIT();     // initial staging + zeros visible cluster-wide

    for (int step = 0; step < Ssz; ++step) {
        const int  tt = dir ? (Ssz - 1 - step) : step;
        const bool pf = (step + 1 < Ssz);
        const uint32_t rdo = (step & 1) ? CBUF : 0u;   // read-buffer offset
        const uint32_t wro = CBUF - rdo;               // write-buffer offset

        // prefetch next x into registers
        float4 p0, p1;
        if (pf) {
            const int ttn = dir ? (tt - 1) : (tt + 1);
            const float4* src = (const float4*)(x + (size_t)kq * Ssz * Dsz
                                                  + (size_t)ttn * Dsz + bg + 8 * xh);
            p0 = src[0]; p1 = src[1];
        }

        const uint32_t cbB = smb + CB + rdo + b_lane;

        // ---- GEMM: 24 uniform kt, W 2-term fp16, 4 accumulator chains ----
        float t0H[4] = {0,0,0,0}, t0L[4] = {0,0,0,0};
        float t1H[4] = {0,0,0,0}, t1L[4] = {0,0,0,0};
        #pragma unroll
        for (int kt = 0; kt < 24; ++kt) {
            uint32_t f0,f1,f2,f3, g0,g1,g2,g3;
            uint32_t q0,q1,q2,q3, r0,r1,r2,r3;
            uint32_t cc0,cc1;
            uint32_t a0 = aH0 + (uint32_t)kt * 512u;
            uint32_t a1 = aH1 + (uint32_t)kt * 512u;
            LDSM4(f0,f1,f2,f3, a0);
            LDSM4(g0,g1,g2,g3, a0 + ASZ);
            LDSM4(q0,q1,q2,q3, a1);
            LDSM4(r0,r1,r2,r3, a1 + ASZ);
            LDSM2T(cc0,cc1, cbB + (uint32_t)kt * 512u);
            MMAF16(t0H, f0,f1,f2,f3, cc0,cc1);
            MMAF16(t1H, q0,q1,q2,q3, cc0,cc1);
            MMAF16(t0L, g0,g1,g2,g3, cc0,cc1);
            MMAF16(t1L, r0,r1,r2,r3, cc0,cc1);
        }

        // ---- in-register epilogue ----
        float zF0 = t0H[0] + t0L[0], zF1 = t0H[1] + t0L[1];
        float zI0 = t0H[2] + t0L[2], zI1 = t0H[3] + t0L[3];
        float zC0 = t1H[0] + t1L[0], zC1 = t1H[1] + t1L[1];
        float zO0 = t1H[2] + t1L[2], zO1 = t1H[3] + t1L[3];

        float f0s = sigm(zF0 + bF),   f1s = sigm(zF1 + bF);
        float i0s = sigm(zI0 + bI),   i1s = sigm(zI1 + bI);
        float g0s = tanhf_(zC0 + bC), g1s = tanhf_(zC1 + bC);
        float o0s = sigm(zO0 + bO),   o1s = sigm(zO1 + bO);

        c0s = f0s * c0s + i0s * g0s;
        c1s = f1s * c1s + i1s * g1s;
        float h0 = o0s * tanhf_(c0s);
        float h1 = o1s * tanhf_(c1s);

        if (pf) {
            // push h pair (ONE b32, fp16x2) into all 8 CTAs' write buffer
            __half2 hp = __floats2half2_rn(h0, h1);
            uint32_t pv = *(uint32_t*)&hp;
            #pragma unroll
            for (int p = 0; p < CL; ++p) {
                asm volatile("st.shared::cluster.b32 [%0],%1;"
                             :: "r"(rHi[p] + wro), "r"(pv) : "memory");
            }
            // stage x(t+1) fp16 into own write buffer
            uint32_t wv[4];
            #pragma unroll
            for (int i = 0; i < 4; ++i) {
                float a = (i < 2) ? ((const float*)&p0)[2*i]   : ((const float*)&p1)[2*i-4];
                float b = (i < 2) ? ((const float*)&p0)[2*i+1] : ((const float*)&p1)[2*i-3];
                __half2 hx = __floats2half2_rn(a, b);
                wv[i] = *(uint32_t*)&hx;
            }
            *(uint4*)(smc + xdst + wro) = make_uint4(wv[0], wv[1], wv[2], wv[3]);
        }

        // single cluster round; out-stores hide the propagation
        CARRIVE();
        {
            size_t ob = ((size_t)(bg + c0) * Ssz + (size_t)tt) * (2 * Hsz)
                      + (size_t)dir * Hsz + hg;
            out[ob]                         = h0;
            out[ob + (size_t)Ssz * 2 * Hsz] = h1;
            if (!pf && write_states) {
                size_t hb = (size_t)OUT_MAIN
                          + ((size_t)dir * Bsz + bg + c0) * Hsz + hg;
                out[hb]       = h0;
                out[hb + Hsz] = h1;
                size_t cb2 = hb + 2 * (size_t)Bsz * Hsz;
                out[cb2]       = c0s;
                out[cb2 + Hsz] = c1s;
            }
        }
        CWAIT();
    }

    // keep cluster alive until everyone is done touching DSMEM
    CARRIVE(); CWAIT();
}

extern "C" void kernel_launch(void* const* d_in, const int* in_sizes, int n_in,
                              void* d_out, int out_size)
{
    const float* x  = (const float*)d_in[0];
    const float* Wf = (const float*)d_in[1];
    const float* bf = (const float*)d_in[2];
    const float* Wb = (const float*)d_in[3];
    const float* bb = (const float*)d_in[4];

    cudaFuncSetAttribute(bilstm_u16,
                         cudaFuncAttributeMaxDynamicSharedMemorySize, SMEM_DYN);

    int ws = ((long long)out_size >= OUT_FULL) ? 1 : 0;
    bilstm_u16<<<128, 256, SMEM_DYN>>>(x, Wf, bf, Wb, bb, (float*)d_out, ws);
}

// round 17
// speedup vs baseline: 9.0337x; 2.7394x over previous
#include <cuda_runtime.h>
#include <cuda_fp16.h>
#include <cstdint>

// ---------------------------------------------------------------------------
// BiLSTM B=128,S=1024,D=128,H=256 — R17: cluster=4 (64 hidden/CTA, 8 batch/
// cluster), fp16 single-term W x fp16 concat, one cluster round per step.
//
// concat[b,k] = x[k,t,b] (k<128) | h[b,k-128]   (source transpose quirk)
//
// 32 clusters x 4 CTAs (1 CTA/SM, 208896 B smem). CTA owns 64 hidden units
// (256 gate rows) of W as fp16 gate-interleaved packed ldmatrix tiles
// (16 row-tiles x 24 k-tiles x 512 B). Concat C fp16, PING-PONG buffered
// (24 kt x 256 B per buffer; kt 0..7 = x, 8..23 = h). Per warp per step:
// 24 kt x (2 LDSM4 + 1 LDSM2T + 2 MMAF16) = 48 MMAs, 4 accumulator chains.
// In-register epilogue (thread holds all 4 gates for one hidden x 2 batches);
// h pushed as ONE fp16x2 b32 to 4 peer CTAs. One cluster arrive/wait per
// step, out-stores inside the window. Sync primitives: proven set only.
// ---------------------------------------------------------------------------

namespace {
constexpr int Bsz = 128, Ssz = 1024, Dsz = 128, Hsz = 256, Ksz = 384;
constexpr int CL = 4;          // CTAs per cluster
constexpr int NH = 64;         // hidden units per CTA
constexpr int NB = 8;          // batches per cluster

constexpr uint32_t ASZ   = 256 * 384 * 2;        // 196608: W fp16 packed
constexpr uint32_t CB    = ASZ;                  // concat buffers base
constexpr uint32_t CBUF  = 24 * 256;             // 6144 per buffer
constexpr int SMEM_DYN   = (int)(CB + 2 * CBUF); // 208896

constexpr long long OUT_MAIN = (long long)Bsz * Ssz * 2 * Hsz;
constexpr long long OUT_FULL = OUT_MAIN + 4LL * Bsz * Hsz;
}

__device__ __forceinline__ uint32_t smem_u32(const void* p) {
    uint32_t a;
    asm("{ .reg .u64 t; cvta.to.shared.u64 t, %1; cvt.u32.u64 %0, t; }"
        : "=r"(a) : "l"(p));
    return a;
}

// A packed-tile offset: packed row r in [0,256), col-tile kt in [0,24),
// col kk in [0,16). tile t = r>>4; per (t,kt) 512B: four 8x8 b16 matrices,
// m = (kk>>3)*2 + (rr>>3).
__device__ __forceinline__ uint32_t aoff_g(int r, int kt, int kk) {
    uint32_t t = (uint32_t)(r >> 4), rr = (uint32_t)(r & 15);
    uint32_t m = (((uint32_t)kk >> 3) << 1) + (rr >> 3);
    return (t * 24u + (uint32_t)kt) * 512u + m * 128u
         + (rr & 7u) * 16u + ((uint32_t)kk & 7u) * 2u;
}
// C offset within a buffer: row k in [0,384), col b in [0,8).
__device__ __forceinline__ uint32_t coff(int k, int b) {
    uint32_t kt = (uint32_t)(k >> 4), kk = (uint32_t)(k & 15);
    return kt * 256u + (kk >> 3) * 128u + (kk & 7u) * 16u + (uint32_t)b * 2u;
}

__device__ __forceinline__ float sigm(float v) {
    return __fdividef(1.0f, 1.0f + __expf(-v));
}
__device__ __forceinline__ float tanhf_(float v) {
    return 1.0f - __fdividef(2.0f, __expf(2.0f * v) + 1.0f);
}

#define LDSM4(r0,r1,r2,r3,addr) \
    asm volatile("ldmatrix.sync.aligned.m8n8.x4.shared.b16 {%0,%1,%2,%3},[%4];" \
        : "=r"(r0),"=r"(r1),"=r"(r2),"=r"(r3) : "r"(addr))
#define LDSM2T(r0,r1,addr) \
    asm volatile("ldmatrix.sync.aligned.m8n8.x2.trans.shared.b16 {%0,%1},[%2];" \
        : "=r"(r0),"=r"(r1) : "r"(addr))
#define MMAF16(d,a0,a1,a2,a3,b0,b1) \
    asm volatile("mma.sync.aligned.m16n8k16.row.col.f32.f16.f16.f32 " \
        "{%0,%1,%2,%3},{%4,%5,%6,%7},{%8,%9},{%0,%1,%2,%3};" \
        : "+f"((d)[0]),"+f"((d)[1]),"+f"((d)[2]),"+f"((d)[3]) \
        : "r"(a0),"r"(a1),"r"(a2),"r"(a3),"r"(b0),"r"(b1))
#define CARRIVE() asm volatile("barrier.cluster.arrive.aligned;" ::: "memory")
#define CWAIT()   asm volatile("barrier.cluster.wait.aligned;"   ::: "memory")

__global__ void __launch_bounds__(256, 1) __cluster_dims__(CL, 1, 1)
bilstm_c4(const float* __restrict__ x,
          const float* __restrict__ Wf, const float* __restrict__ bf,
          const float* __restrict__ Wb, const float* __restrict__ bb,
          float* __restrict__ out, int write_states)
{
    extern __shared__ char smc[];
    const uint32_t smb = smem_u32(smc);

    const int tid  = threadIdx.x;
    const int wid  = tid >> 5;
    const int lane = tid & 31;
    uint32_t myrank;
    asm("mov.u32 %0, %%cluster_ctarank;" : "=r"(myrank));
    const int rank = (int)myrank;
    const int cid  = blockIdx.x >> 2;       // cluster id (0..31)
    const int dir  = cid >> 4;              // 0 fwd, 1 bwd
    const int bg   = (cid & 15) * NB;       // first batch of this cluster

    const float* W    = dir ? Wb : Wf;
    const float* bias = dir ? bb : bf;

    // ---- W slice -> gate-interleaved packed fp16 A tiles ----
    // source row r = g*64 + jl (jl = local hidden 0..63);
    // packed rp = (jl>>3)*32 + (g>>1)*16 + (g&1)*8 + (jl&7)
    for (int idx = tid; idx < 256 * Ksz; idx += 256) {
        int r = idx / Ksz, k = idx - r * Ksz;
        int g = r >> 6, jl = r & 63;
        int rp = ((jl >> 3) << 5) + ((g >> 1) << 4) + ((g & 1) << 3) + (jl & 7);
        int gr = g * Hsz + rank * NH + jl;
        float v = W[(size_t)gr * Ksz + k];
        *(uint16_t*)(smc + aoff_g(rp, k >> 4, k & 15)) =
            __half_as_ushort(__float2half(v));
    }
    // zero both concat buffers (h(0) = 0)
    for (int i = tid; i < (int)(2 * CBUF) / 4; i += 256)
        ((uint32_t*)(smc + CB))[i] = 0;
    __syncthreads();

    // ---- x staging: thread t<128 owns k-row kq = t (8 batches = 16B) ----
    const int kq = tid;          // valid when tid < 128
    const uint32_t xdst = CB + coff(kq & 127, 0);
    if (tid < Dsz) {
        int tt0 = dir ? (Ssz - 1) : 0;
        const float4* src = (const float4*)(x + (size_t)kq * Ssz * Dsz
                                              + (size_t)tt0 * Dsz + bg);
        float4 v0 = src[0], v1 = src[1];
        uint32_t wv[4];
        #pragma unroll
        for (int i = 0; i < 4; ++i) {
            float a = (i < 2) ? ((const float*)&v0)[2*i]   : ((const float*)&v1)[2*i-4];
            float b = (i < 2) ? ((const float*)&v0)[2*i+1] : ((const float*)&v1)[2*i-3];
            __half2 hp = __floats2half2_rn(a, b);
            wv[i] = *(uint32_t*)&hp;
        }
        *(uint4*)(smc + xdst) = make_uint4(wv[0], wv[1], wv[2], wv[3]);  // buf 0
    }

    // ---- per-thread ownership: hidden hh = 8*wid + lane/4, cols c0,c0+1 ----
    const int hh = 8 * wid + (lane >> 2);
    const int hg = rank * NH + hh;          // global hidden unit
    const int c0 = 2 * (lane & 3);          // batch col pair within group
    const float bF = bias[0 * Hsz + hg], bI = bias[1 * Hsz + hg],
                bC = bias[2 * Hsz + hg], bO = bias[3 * Hsz + hg];

    // DSMEM push addresses (buffer 0): h at coff(128+hg, c0), 4 peers
    uint32_t rHi[CL];
    {
        uint32_t loc = smb + CB + coff(Dsz + hg, c0);
        #pragma unroll
        for (int p = 0; p < CL; ++p)
            asm("mapa.shared::cluster.u32 %0,%1,%2;" : "=r"(rHi[p]) : "r"(loc), "r"(p));
    }

    // GEMM per-lane bases: warp w owns tiles 2w ([f|i]) and 2w+1 ([c|o])
    const uint32_t a_lane = (uint32_t)(lane >> 3) * 128u + (uint32_t)(lane & 7) * 16u;
    const uint32_t aT0 = smb + (uint32_t)wid * 24576u + a_lane;
    const uint32_t aT1 = aT0 + 12288u;
    const uint32_t b_lane = (uint32_t)(lane & 15) * 16u;

    float c0s = 0.f, c1s = 0.f;

    __syncthreads();
    CARRIVE(); CWAIT();     // initial staging + zeros visible cluster-wide

    for (int step = 0; step < Ssz; ++step) {
        const int  tt = dir ? (Ssz - 1 - step) : step;
        const bool pf = (step + 1 < Ssz);
        const uint32_t rdo = (step & 1) ? CBUF : 0u;   // read-buffer offset
        const uint32_t wro = CBUF - rdo;               // write-buffer offset

        // prefetch next x into registers
        float4 p0, p1;
        if (pf && tid < Dsz) {
            const int ttn = dir ? (tt - 1) : (tt + 1);
            const float4* src = (const float4*)(x + (size_t)kq * Ssz * Dsz
                                                  + (size_t)ttn * Dsz + bg);
            p0 = src[0]; p1 = src[1];
        }

        const uint32_t cbB = smb + CB + rdo + b_lane;

        // ---- GEMM: 24 kt x (2 LDSM4 + 1 LDSM2T + 2 MMA), 4 chains ----
        float t0a[4] = {0,0,0,0}, t0b[4] = {0,0,0,0};
        float t1a[4] = {0,0,0,0}, t1b[4] = {0,0,0,0};
        #pragma unroll
        for (int kt = 0; kt < 24; kt += 2) {
            uint32_t f0,f1,f2,f3, q0,q1,q2,q3, cc0,cc1;
            uint32_t g0,g1,g2,g3, r0,r1,r2,r3, dd0,dd1;
            uint32_t a0 = aT0 + (uint32_t)kt * 512u;
            uint32_t a1 = aT1 + (uint32_t)kt * 512u;
            LDSM4(f0,f1,f2,f3, a0);
            LDSM4(q0,q1,q2,q3, a1);
            LDSM2T(cc0,cc1, cbB + (uint32_t)kt * 256u);
            LDSM4(g0,g1,g2,g3, a0 + 512u);
            LDSM4(r0,r1,r2,r3, a1 + 512u);
            LDSM2T(dd0,dd1, cbB + (uint32_t)kt * 256u + 256u);
            MMAF16(t0a, f0,f1,f2,f3, cc0,cc1);
            MMAF16(t1a, q0,q1,q2,q3, cc0,cc1);
            MMAF16(t0b, g0,g1,g2,g3, dd0,dd1);
            MMAF16(t1b, r0,r1,r2,r3, dd0,dd1);
        }

        // ---- in-register epilogue: thread holds f,i,c,o for (hh, c0..c0+1) ----
        float zF0 = t0a[0] + t0b[0], zF1 = t0a[1] + t0b[1];
        float zI0 = t0a[2] + t0b[2], zI1 = t0a[3] + t0b[3];
        float zC0 = t1a[0] + t1b[0], zC1 = t1a[1] + t1b[1];
        float zO0 = t1a[2] + t1b[2], zO1 = t1a[3] + t1b[3];

        float f0s = sigm(zF0 + bF),   f1s = sigm(zF1 + bF);
        float i0s = sigm(zI0 + bI),   i1s = sigm(zI1 + bI);
        float g0s = tanhf_(zC0 + bC), g1s = tanhf_(zC1 + bC);
        float o0s = sigm(zO0 + bO),   o1s = sigm(zO1 + bO);

        c0s = f0s * c0s + i0s * g0s;
        c1s = f1s * c1s + i1s * g1s;
        float h0 = o0s * tanhf_(c0s);
        float h1 = o1s * tanhf_(c1s);

        if (pf) {
            // push h pair (ONE b32, fp16x2) into all 4 CTAs' write buffer
            __half2 hp = __floats2half2_rn(h0, h1);
            uint32_t pv = *(uint32_t*)&hp;
            #pragma unroll
            for (int p = 0; p < CL; ++p) {
                asm volatile("st.shared::cluster.b32 [%0],%1;"
                             :: "r"(rHi[p] + wro), "r"(pv) : "memory");
            }
            // stage x(t+1) fp16 into own write buffer
            if (tid < Dsz) {
                uint32_t wv[4];
                #pragma unroll
                for (int i = 0; i < 4; ++i) {
                    float a = (i < 2) ? ((const float*)&p0)[2*i]   : ((const float*)&p1)[2*i-4];
                    float b = (i < 2) ? ((const float*)&p0)[2*i+1] : ((const float*)&p1)[2*i-3];
                    __half2 hx = __floats2half2_rn(a, b);
                    wv[i] = *(uint32_t*)&hx;
                }
                *(uint4*)(smc + xdst + wro) = make_uint4(wv[0], wv[1], wv[2], wv[3]);
            }
        }

        // single cluster round; out-stores hide the propagation
        CARRIVE();
        {
            size_t ob = ((size_t)(bg + c0) * Ssz + (size_t)tt) * (2 * Hsz)
                      + (size_t)dir * Hsz + hg;
            out[ob]                         = h0;
            out[ob + (size_t)Ssz * 2 * Hsz] = h1;
            if (!pf && write_states) {
                size_t hb = (size_t)OUT_MAIN
                          + ((size_t)dir * Bsz + bg + c0) * Hsz + hg;
                out[hb]       = h0;
                out[hb + Hsz] = h1;
                size_t cb2 = hb + 2 * (size_t)Bsz * Hsz;
                out[cb2]       = c0s;
                out[cb2 + Hsz] = c1s;
            }
        }
        CWAIT();
    }

    // keep cluster alive until everyone is done touching DSMEM
    CARRIVE(); CWAIT();
}

extern "C" void kernel_launch(void* const* d_in, const int* in_sizes, int n_in,
                              void* d_out, int out_size)
{
    const float* x  = (const float*)d_in[0];
    const float* Wf = (const float*)d_in[1];
    const float* bf = (const float*)d_in[2];
    const float* Wb = (const float*)d_in[3];
    const float* bb = (const float*)d_in[4];

    cudaFuncSetAttribute(bilstm_c4,
                         cudaFuncAttributeMaxDynamicSharedMemorySize, SMEM_DYN);

    int ws = ((long long)out_size >= OUT_FULL) ? 1 : 0;
    bilstm_c4<<<128, 256, SMEM_DYN>>>(x, Wf, bf, Wb, bb, (float*)d_out, ws);
}